// round 1
// baseline (speedup 1.0000x reference)
#include <cuda_runtime.h>
#include <math.h>

#define T_  2048
#define B_  2
#define E_  512
#define H_  8
#define D_  64
#define E3_ 1536

// ---- scratch (__device__ globals: allocation-guard-legal) ----
__device__ float g_q[B_*H_*T_*D_];            // [B,H,T,D]
__device__ float g_k[B_*H_*T_*D_];
__device__ float g_v[B_*H_*T_*D_];
__device__ float g_r[H_*T_*D_];               // [H,R,D]
__device__ float g_S [(size_t)B_*H_*T_*T_];   // scores -> attn (in place)
__device__ float g_BD[(size_t)B_*H_*T_*T_];   // raw BD scores
__device__ float g_ctx[T_*B_*E_];             // [T,B,E]

// ============================================================
// QKV projection: C[m,n] = input[m,:]·W[n,:] + bias[n]
// m = t*B+b (input layout [T,B,E]); n -> {q,k,v}[B,H,T,D]
// ============================================================
__global__ __launch_bounds__(256) void k_qkv(const float* __restrict__ A,
                                             const float* __restrict__ W,
                                             const float* __restrict__ bias) {
    __shared__ float As[64][17];
    __shared__ float Bs[64][17];
    const int K = E_;
    const int m0 = blockIdx.y * 64, n0 = blockIdx.x * 64;
    const int tx = threadIdx.x, ty = threadIdx.y;
    const int tid = ty * 16 + tx;
    float acc[4][4] = {};

    for (int k0 = 0; k0 < K; k0 += 16) {
        #pragma unroll
        for (int l = 0; l < 4; l++) {
            int idx = tid + l * 256;
            int row = idx >> 4, kk = idx & 15;
            As[row][kk] = A[(m0 + row) * K + k0 + kk];
            Bs[row][kk] = W[(n0 + row) * K + k0 + kk];
        }
        __syncthreads();
        #pragma unroll
        for (int kk = 0; kk < 16; kk++) {
            float a[4], b[4];
            #pragma unroll
            for (int i = 0; i < 4; i++) a[i] = As[ty*4+i][kk];
            #pragma unroll
            for (int j = 0; j < 4; j++) b[j] = Bs[tx*4+j][kk];
            #pragma unroll
            for (int i = 0; i < 4; i++)
                #pragma unroll
                for (int j = 0; j < 4; j++) acc[i][j] += a[i] * b[j];
        }
        __syncthreads();
    }
    #pragma unroll
    for (int i = 0; i < 4; i++) {
        int m = m0 + ty*4 + i;
        int t = m / B_, b = m % B_;
        #pragma unroll
        for (int j = 0; j < 4; j++) {
            int n = n0 + tx*4 + j;
            float v = acc[i][j] + bias[n];
            int sec = n >> 9, h = (n & 511) >> 6, d = n & 63;
            float* dst = (sec == 0) ? g_q : (sec == 1) ? g_k : g_v;
            dst[(((size_t)(b*H_ + h) * T_) + t) * D_ + d] = v;
        }
    }
}

// ============================================================
// pos projection: r[rr,n] = pos[rr,:]·Wp[n,:] + bp[n] -> g_r[H,R,D]
// ============================================================
__global__ __launch_bounds__(256) void k_pos(const float* __restrict__ A,
                                             const float* __restrict__ W,
                                             const float* __restrict__ bias) {
    __shared__ float As[64][17];
    __shared__ float Bs[64][17];
    const int K = E_;
    const int m0 = blockIdx.y * 64, n0 = blockIdx.x * 64;
    const int tx = threadIdx.x, ty = threadIdx.y;
    const int tid = ty * 16 + tx;
    float acc[4][4] = {};

    for (int k0 = 0; k0 < K; k0 += 16) {
        #pragma unroll
        for (int l = 0; l < 4; l++) {
            int idx = tid + l * 256;
            int row = idx >> 4, kk = idx & 15;
            As[row][kk] = A[(m0 + row) * K + k0 + kk];
            Bs[row][kk] = W[(n0 + row) * K + k0 + kk];
        }
        __syncthreads();
        #pragma unroll
        for (int kk = 0; kk < 16; kk++) {
            float a[4], b[4];
            #pragma unroll
            for (int i = 0; i < 4; i++) a[i] = As[ty*4+i][kk];
            #pragma unroll
            for (int j = 0; j < 4; j++) b[j] = Bs[tx*4+j][kk];
            #pragma unroll
            for (int i = 0; i < 4; i++)
                #pragma unroll
                for (int j = 0; j < 4; j++) acc[i][j] += a[i] * b[j];
        }
        __syncthreads();
    }
    #pragma unroll
    for (int i = 0; i < 4; i++) {
        int rr = m0 + ty*4 + i;
        #pragma unroll
        for (int j = 0; j < 4; j++) {
            int n = n0 + tx*4 + j;
            int h = n >> 6, d = n & 63;
            g_r[((size_t)h * T_ + rr) * D_ + d] = acc[i][j] + bias[n];
        }
    }
}

// ============================================================
// Scores: S/BD[bh,t,s] = sum_d (q[bh,t,d]+bias_h[d]) * Bmat[s,d]
// use_r=0: Bmat = k[bh]  -> g_S ;  use_r=1: Bmat = r[h] -> g_BD
// ============================================================
__global__ __launch_bounds__(256) void k_score(const float* __restrict__ hbias,
                                               int use_r) {
    const int bh = blockIdx.z;
    const int h = bh % H_;
    const float* Aq = g_q + (size_t)bh * T_ * D_;
    const float* Bm = use_r ? (g_r + (size_t)h * T_ * D_)
                            : (g_k + (size_t)bh * T_ * D_);
    float* out = (use_r ? g_BD : g_S) + (size_t)bh * T_ * T_;
    const float* bias = hbias + h * D_;

    __shared__ float As[64][17];
    __shared__ float Bs[64][17];
    const int t0 = blockIdx.y * 64, s0 = blockIdx.x * 64;
    const int tx = threadIdx.x, ty = threadIdx.y;
    const int tid = ty * 16 + tx;
    float acc[4][4] = {};

    for (int k0 = 0; k0 < D_; k0 += 16) {
        #pragma unroll
        for (int l = 0; l < 4; l++) {
            int idx = tid + l * 256;
            int row = idx >> 4, kk = idx & 15;
            As[row][kk] = Aq[(t0 + row) * D_ + k0 + kk] + bias[k0 + kk];
            Bs[row][kk] = Bm[(s0 + row) * D_ + k0 + kk];
        }
        __syncthreads();
        #pragma unroll
        for (int kk = 0; kk < 16; kk++) {
            float a[4], b[4];
            #pragma unroll
            for (int i = 0; i < 4; i++) a[i] = As[ty*4+i][kk];
            #pragma unroll
            for (int j = 0; j < 4; j++) b[j] = Bs[tx*4+j][kk];
            #pragma unroll
            for (int i = 0; i < 4; i++)
                #pragma unroll
                for (int j = 0; j < 4; j++) acc[i][j] += a[i] * b[j];
        }
        __syncthreads();
    }
    #pragma unroll
    for (int i = 0; i < 4; i++) {
        int t = t0 + ty*4 + i;
        #pragma unroll
        for (int j = 0; j < 4; j++)
            out[(size_t)t * T_ + s0 + tx*4 + j] = acc[i][j];
    }
}

// ============================================================
// Softmax with analytic rel_shift:
//   s<=t   : + BD[t, T-1-t+s]
//   s==t+1 : + 0
//   s>t+1  : + BD[t+1, s-t-2]
// ============================================================
__global__ __launch_bounds__(256) void k_softmax() {
    const float scale = 0.125f;  // 1/sqrt(64)
    const int row = blockIdx.x;            // bh*T + t
    const int t = row & (T_ - 1);
    float* Srow = g_S + (size_t)row * T_;
    const float* BDt = g_BD + (size_t)row * T_;   // row t of this (b,h)
    const int tid = threadIdx.x;
    __shared__ float red[256];

    float vals[8];
    float mx = -1e30f;
    #pragma unroll
    for (int i = 0; i < 8; i++) {
        int s = tid + i * 256;
        float v = Srow[s];
        if (s <= t)          v += BDt[T_ - 1 - t + s];
        else if (s > t + 1)  v += BDt[T_ + (s - t - 2)];  // row t+1
        v *= scale;
        vals[i] = v;
        mx = fmaxf(mx, v);
    }
    red[tid] = mx; __syncthreads();
    for (int off = 128; off > 0; off >>= 1) {
        if (tid < off) red[tid] = fmaxf(red[tid], red[tid + off]);
        __syncthreads();
    }
    mx = red[0]; __syncthreads();

    float sum = 0.f;
    #pragma unroll
    for (int i = 0; i < 8; i++) {
        float v = expf(vals[i] - mx);
        vals[i] = v;
        sum += v;
    }
    red[tid] = sum; __syncthreads();
    for (int off = 128; off > 0; off >>= 1) {
        if (tid < off) red[tid] += red[tid + off];
        __syncthreads();
    }
    float inv = 1.f / red[0];
    #pragma unroll
    for (int i = 0; i < 8; i++)
        Srow[tid + i * 256] = vals[i] * inv;
}

// ============================================================
// ctx[t,b,h*64+d] = sum_s attn[bh,t,s] * v[bh,s,d]
// ============================================================
__global__ __launch_bounds__(256) void k_av() {
    const int bh = blockIdx.z;
    const int b = bh / H_, h = bh % H_;
    const float* P = g_S + (size_t)bh * T_ * T_;
    const float* V = g_v + (size_t)bh * T_ * D_;

    __shared__ float As[64][17];
    __shared__ float Bs[16][64];
    const int t0 = blockIdx.y * 64;
    const int tx = threadIdx.x, ty = threadIdx.y;
    const int tid = ty * 16 + tx;
    float acc[4][4] = {};

    for (int k0 = 0; k0 < T_; k0 += 16) {
        #pragma unroll
        for (int l = 0; l < 4; l++) {
            int idx = tid + l * 256;
            int row = idx >> 4, kk = idx & 15;
            As[row][kk] = P[(size_t)(t0 + row) * T_ + k0 + kk];
            int kb = idx >> 6, col = idx & 63;
            Bs[kb][col] = V[(k0 + kb) * D_ + col];
        }
        __syncthreads();
        #pragma unroll
        for (int kk = 0; kk < 16; kk++) {
            float a[4], b[4];
            #pragma unroll
            for (int i = 0; i < 4; i++) a[i] = As[ty*4+i][kk];
            #pragma unroll
            for (int j = 0; j < 4; j++) b[j] = Bs[kk][tx*4+j];
            #pragma unroll
            for (int i = 0; i < 4; i++)
                #pragma unroll
                for (int j = 0; j < 4; j++) acc[i][j] += a[i] * b[j];
        }
        __syncthreads();
    }
    #pragma unroll
    for (int i = 0; i < 4; i++) {
        int t = t0 + ty*4 + i;
        #pragma unroll
        for (int j = 0; j < 4; j++) {
            int d = tx*4 + j;
            g_ctx[((size_t)t * B_ + b) * E_ + h * D_ + d] = acc[i][j];
        }
    }
}

// ============================================================
// out projection: out[m,n] = ctx[m,:]·Wout[n,:] + bout[n]
// ============================================================
__global__ __launch_bounds__(256) void k_out(const float* __restrict__ W,
                                             const float* __restrict__ bias,
                                             float* __restrict__ out) {
    __shared__ float As[64][17];
    __shared__ float Bs[64][17];
    const int K = E_;
    const int m0 = blockIdx.y * 64, n0 = blockIdx.x * 64;
    const int tx = threadIdx.x, ty = threadIdx.y;
    const int tid = ty * 16 + tx;
    float acc[4][4] = {};

    for (int k0 = 0; k0 < K; k0 += 16) {
        #pragma unroll
        for (int l = 0; l < 4; l++) {
            int idx = tid + l * 256;
            int row = idx >> 4, kk = idx & 15;
            As[row][kk] = g_ctx[(m0 + row) * K + k0 + kk];
            Bs[row][kk] = W[(n0 + row) * K + k0 + kk];
        }
        __syncthreads();
        #pragma unroll
        for (int kk = 0; kk < 16; kk++) {
            float a[4], b[4];
            #pragma unroll
            for (int i = 0; i < 4; i++) a[i] = As[ty*4+i][kk];
            #pragma unroll
            for (int j = 0; j < 4; j++) b[j] = Bs[tx*4+j][kk];
            #pragma unroll
            for (int i = 0; i < 4; i++)
                #pragma unroll
                for (int j = 0; j < 4; j++) acc[i][j] += a[i] * b[j];
        }
        __syncthreads();
    }
    #pragma unroll
    for (int i = 0; i < 4; i++) {
        int m = m0 + ty*4 + i;
        #pragma unroll
        for (int j = 0; j < 4; j++) {
            int n = n0 + tx*4 + j;
            out[(size_t)m * E_ + n] = acc[i][j] + bias[n];
        }
    }
}

// ============================================================
extern "C" void kernel_launch(void* const* d_in, const int* in_sizes, int n_in,
                              void* d_out, int out_size) {
    const float* input = (const float*)d_in[0];
    const float* pos   = (const float*)d_in[1];
    const float* w_in  = (const float*)d_in[2];
    const float* w_out = (const float*)d_in[3];
    const float* w_pos = (const float*)d_in[4];
    const float* b_in  = (const float*)d_in[5];
    const float* b_out = (const float*)d_in[6];
    const float* b_pos = (const float*)d_in[7];
    const float* rwb   = (const float*)d_in[8];
    const float* rrb   = (const float*)d_in[9];
    float* out = (float*)d_out;

    dim3 thr(16, 16);
    k_qkv<<<dim3(E3_/64, (T_*B_)/64), thr>>>(input, w_in, b_in);
    k_pos<<<dim3(E_/64,  T_/64),      thr>>>(pos, w_pos, b_pos);
    k_score<<<dim3(T_/64, T_/64, B_*H_), thr>>>(rwb, 0);
    k_score<<<dim3(T_/64, T_/64, B_*H_), thr>>>(rrb, 1);
    k_softmax<<<B_*H_*T_, 256>>>();
    k_av<<<dim3(1, T_/64, B_*H_), thr>>>();
    k_out<<<dim3(E_/64, (T_*B_)/64), thr>>>(w_out, b_out, out);
}

// round 2
// speedup vs baseline: 2.2270x; 2.2270x over previous
#include <cuda_runtime.h>
#include <math.h>

#define T_  2048
#define B_  2
#define E_  512
#define H_  8
#define D_  64
#define E3_ 1536

// ---- scratch (__device__ globals: allocation-guard-legal) ----
__device__ float g_q[B_*H_*T_*D_];            // [B,H,T,D]
__device__ float g_k[B_*H_*T_*D_];
__device__ float g_v[B_*H_*T_*D_];
__device__ float g_r[H_*T_*D_];               // [H,R,D]
__device__ float g_S [(size_t)B_*H_*T_*T_];   // scores -> attn (in place)
__device__ float g_BD[(size_t)B_*H_*T_*T_];   // raw BD scores
__device__ float g_ctx[T_*B_*E_];             // [T,B,E]

__device__ __forceinline__ unsigned f2tf32(float x) {
    unsigned r;
    asm("cvt.rna.tf32.f32 %0, %1;" : "=r"(r) : "f"(x));
    return r;
}

#define MMA8(d, a, b) \
  asm volatile("mma.sync.aligned.m16n8k8.row.col.f32.tf32.tf32.f32 " \
      "{%0,%1,%2,%3},{%4,%5,%6,%7},{%8,%9},{%0,%1,%2,%3};" \
      : "+f"((d)[0]), "+f"((d)[1]), "+f"((d)[2]), "+f"((d)[3]) \
      : "r"((a)[0]), "r"((a)[1]), "r"((a)[2]), "r"((a)[3]), \
        "r"((b)[0]), "r"((b)[1]))

// ============================================================
// Shared mainloop: C[128,128] = A[m0:,:]·Bt[n0:,:]^T, both K-contiguous.
// 256 threads = 8 warps (2x4), warp tile 64x32 (4 m-tiles x 4 n-tiles).
// ============================================================
template<int KTOT, bool ABIAS>
__device__ __forceinline__ void gemm_nt_main(const float* __restrict__ A, int lda,
                                             const float* __restrict__ Bt, int ldb,
                                             int m0, int n0,
                                             const float* __restrict__ abias,
                                             float acc[4][4][4]) {
    __shared__ unsigned As[128][36];
    __shared__ unsigned Bs[128][36];
    const int tid = threadIdx.x;
    const int lane = tid & 31, warp = tid >> 5;
    const int wm = (warp >> 2) * 64, wn = (warp & 3) * 32;

    for (int k0 = 0; k0 < KTOT; k0 += 32) {
        #pragma unroll
        for (int i = 0; i < 4; i++) {
            int idx = tid + i * 256;
            int row = idx >> 3, c4 = (idx & 7) * 4;
            float4 va = *(const float4*)(A + (size_t)(m0 + row) * lda + k0 + c4);
            if (ABIAS) {
                va.x += abias[k0 + c4];     va.y += abias[k0 + c4 + 1];
                va.z += abias[k0 + c4 + 2]; va.w += abias[k0 + c4 + 3];
            }
            As[row][c4]   = f2tf32(va.x); As[row][c4+1] = f2tf32(va.y);
            As[row][c4+2] = f2tf32(va.z); As[row][c4+3] = f2tf32(va.w);
            float4 vb = *(const float4*)(Bt + (size_t)(n0 + row) * ldb + k0 + c4);
            Bs[row][c4]   = f2tf32(vb.x); Bs[row][c4+1] = f2tf32(vb.y);
            Bs[row][c4+2] = f2tf32(vb.z); Bs[row][c4+3] = f2tf32(vb.w);
        }
        __syncthreads();
        #pragma unroll
        for (int ks = 0; ks < 4; ks++) {
            const int kk = ks * 8;
            const int r = lane >> 2, c = kk + (lane & 3);
            unsigned af[4][4], bf[4][2];
            #pragma unroll
            for (int mi = 0; mi < 4; mi++) {
                int rr = wm + mi * 16 + r;
                af[mi][0] = As[rr][c];     af[mi][1] = As[rr + 8][c];
                af[mi][2] = As[rr][c + 4]; af[mi][3] = As[rr + 8][c + 4];
            }
            #pragma unroll
            for (int ni = 0; ni < 4; ni++) {
                int rb = wn + ni * 8 + r;
                bf[ni][0] = Bs[rb][c]; bf[ni][1] = Bs[rb][c + 4];
            }
            #pragma unroll
            for (int mi = 0; mi < 4; mi++)
                #pragma unroll
                for (int ni = 0; ni < 4; ni++)
                    MMA8(acc[mi][ni], af[mi], bf[ni]);
        }
        __syncthreads();
    }
}

// epilogue index helpers (m16n8k8 C layout)
#define EPI_ROW(m0, wm, mi, rg) ((m0) + (wm) + (mi)*16 + (lane >> 2) + (((rg) & 2) << 2))
#define EPI_COL(n0, wn, ni, rg) ((n0) + (wn) + (ni)*8 + ((lane & 3) << 1) + ((rg) & 1))

// ============================================================
// QKV projection: [T*B, 3E] = input·Win^T + b, scatter to q/k/v [B,H,T,D]
// ============================================================
__global__ __launch_bounds__(256) void k_qkv(const float* __restrict__ A,
                                             const float* __restrict__ W,
                                             const float* __restrict__ bias) {
    float acc[4][4][4] = {};
    const int m0 = blockIdx.y * 128, n0 = blockIdx.x * 128;
    gemm_nt_main<E_, false>(A, E_, W, E_, m0, n0, nullptr, acc);
    const int lane = threadIdx.x & 31, warp = threadIdx.x >> 5;
    const int wm = (warp >> 2) * 64, wn = (warp & 3) * 32;
    #pragma unroll
    for (int mi = 0; mi < 4; mi++)
        #pragma unroll
        for (int ni = 0; ni < 4; ni++)
            #pragma unroll
            for (int rg = 0; rg < 4; rg++) {
                int row = EPI_ROW(m0, wm, mi, rg);
                int col = EPI_COL(n0, wn, ni, rg);
                float v = acc[mi][ni][rg] + bias[col];
                int t = row / B_, b = row % B_;
                int sec = col >> 9, h = (col >> 6) & 7, d = col & 63;
                float* dst = (sec == 0) ? g_q : (sec == 1) ? g_k : g_v;
                dst[(((size_t)(b * H_ + h) * T_) + t) * D_ + d] = v;
            }
}

// ============================================================
// pos projection -> g_r[H,R,D]
// ============================================================
__global__ __launch_bounds__(256) void k_pos(const float* __restrict__ A,
                                             const float* __restrict__ W,
                                             const float* __restrict__ bias) {
    float acc[4][4][4] = {};
    const int m0 = blockIdx.y * 128, n0 = blockIdx.x * 128;
    gemm_nt_main<E_, false>(A, E_, W, E_, m0, n0, nullptr, acc);
    const int lane = threadIdx.x & 31, warp = threadIdx.x >> 5;
    const int wm = (warp >> 2) * 64, wn = (warp & 3) * 32;
    #pragma unroll
    for (int mi = 0; mi < 4; mi++)
        #pragma unroll
        for (int ni = 0; ni < 4; ni++)
            #pragma unroll
            for (int rg = 0; rg < 4; rg++) {
                int rr = EPI_ROW(m0, wm, mi, rg);
                int col = EPI_COL(n0, wn, ni, rg);
                int h = col >> 6, d = col & 63;
                g_r[((size_t)h * T_ + rr) * D_ + d] = acc[mi][ni][rg] + bias[col];
            }
}

// ============================================================
// Scores (AC & BD fused over z): out[t,s] = (q[t]+bias_h)·Bmat[s]
// z<16 -> AC (Bmat=k, out=g_S), z>=16 -> BD (Bmat=r, out=g_BD)
// ============================================================
__global__ __launch_bounds__(256) void k_score(const float* __restrict__ rwb,
                                               const float* __restrict__ rrb) {
    const int z = blockIdx.z;
    const int use_r = z >> 4, bh = z & 15, h = bh & 7;
    const float* Aq = g_q + (size_t)bh * T_ * D_;
    const float* Bm = use_r ? (g_r + (size_t)h * T_ * D_)
                            : (g_k + (size_t)bh * T_ * D_);
    float* out = (use_r ? g_BD : g_S) + (size_t)bh * T_ * T_;
    const float* bias = (use_r ? rrb : rwb) + h * D_;

    float acc[4][4][4] = {};
    const int m0 = blockIdx.y * 128, n0 = blockIdx.x * 128;
    gemm_nt_main<D_, true>(Aq, D_, Bm, D_, m0, n0, bias, acc);
    const int lane = threadIdx.x & 31, warp = threadIdx.x >> 5;
    const int wm = (warp >> 2) * 64, wn = (warp & 3) * 32;
    #pragma unroll
    for (int mi = 0; mi < 4; mi++)
        #pragma unroll
        for (int ni = 0; ni < 4; ni++)
            #pragma unroll
            for (int rg = 0; rg < 4; rg++) {
                int t = EPI_ROW(m0, wm, mi, rg);
                int s = EPI_COL(n0, wn, ni, rg);
                out[(size_t)t * T_ + s] = acc[mi][ni][rg];
            }
}

// ============================================================
// Softmax with analytic rel_shift:
//   s<=t : +BD[t, T-1-t+s];  s==t+1 : +0;  s>t+1 : +BD[t+1, s-t-2]
// ============================================================
__global__ __launch_bounds__(256) void k_softmax() {
    const float scale = 0.125f;
    const int row = blockIdx.x;            // bh*T + t
    const int t = row & (T_ - 1);
    float* Srow = g_S + (size_t)row * T_;
    const float* BDt = g_BD + (size_t)row * T_;
    const int tid = threadIdx.x;
    __shared__ float red[256];

    float vals[8];
    float mx = -1e30f;
    #pragma unroll
    for (int i = 0; i < 8; i++) {
        int s = tid + i * 256;
        float v = Srow[s];
        if (s <= t)          v += BDt[T_ - 1 - t + s];
        else if (s > t + 1)  v += BDt[T_ + (s - t - 2)];
        v *= scale;
        vals[i] = v;
        mx = fmaxf(mx, v);
    }
    red[tid] = mx; __syncthreads();
    for (int off = 128; off > 0; off >>= 1) {
        if (tid < off) red[tid] = fmaxf(red[tid], red[tid + off]);
        __syncthreads();
    }
    mx = red[0]; __syncthreads();

    float sum = 0.f;
    #pragma unroll
    for (int i = 0; i < 8; i++) {
        float v = expf(vals[i] - mx);
        vals[i] = v;
        sum += v;
    }
    red[tid] = sum; __syncthreads();
    for (int off = 128; off > 0; off >>= 1) {
        if (tid < off) red[tid] += red[tid + off];
        __syncthreads();
    }
    float inv = 1.f / red[0];
    #pragma unroll
    for (int i = 0; i < 8; i++)
        Srow[tid + i * 256] = vals[i] * inv;
}

// ============================================================
// ctx = attn · V : block 128x64, warp tile 32x32 (warps 4x2)
// ============================================================
__global__ __launch_bounds__(256) void k_av() {
    const int bh = blockIdx.y;
    const int b = bh / H_, h = bh % H_;
    const float* P = g_S + (size_t)bh * T_ * T_;
    const float* V = g_v + (size_t)bh * T_ * D_;
    const int t0 = blockIdx.x * 128;

    __shared__ unsigned As[128][36];
    __shared__ unsigned Bs[32][72];
    const int tid = threadIdx.x;
    const int lane = tid & 31, warp = tid >> 5;
    const int wm = (warp >> 1) * 32, wn = (warp & 1) * 32;
    float acc[2][4][4] = {};

    for (int k0 = 0; k0 < T_; k0 += 32) {
        #pragma unroll
        for (int i = 0; i < 4; i++) {
            int idx = tid + i * 256;
            int row = idx >> 3, c4 = (idx & 7) * 4;
            float4 va = *(const float4*)(P + (size_t)(t0 + row) * T_ + k0 + c4);
            As[row][c4]   = f2tf32(va.x); As[row][c4+1] = f2tf32(va.y);
            As[row][c4+2] = f2tf32(va.z); As[row][c4+3] = f2tf32(va.w);
        }
        #pragma unroll
        for (int i = 0; i < 2; i++) {
            int idx = tid + i * 256;
            int row = idx >> 4, c4 = (idx & 15) * 4;
            float4 vb = *(const float4*)(V + (size_t)(k0 + row) * D_ + c4);
            Bs[row][c4]   = f2tf32(vb.x); Bs[row][c4+1] = f2tf32(vb.y);
            Bs[row][c4+2] = f2tf32(vb.z); Bs[row][c4+3] = f2tf32(vb.w);
        }
        __syncthreads();
        #pragma unroll
        for (int ks = 0; ks < 4; ks++) {
            const int kk = ks * 8;
            const int r = lane >> 2, c = kk + (lane & 3);
            unsigned af[2][4], bf[4][2];
            #pragma unroll
            for (int mi = 0; mi < 2; mi++) {
                int rr = wm + mi * 16 + r;
                af[mi][0] = As[rr][c];     af[mi][1] = As[rr + 8][c];
                af[mi][2] = As[rr][c + 4]; af[mi][3] = As[rr + 8][c + 4];
            }
            #pragma unroll
            for (int ni = 0; ni < 4; ni++) {
                int cb = wn + ni * 8 + r;
                bf[ni][0] = Bs[c][cb]; bf[ni][1] = Bs[c + 4][cb];
            }
            #pragma unroll
            for (int mi = 0; mi < 2; mi++)
                #pragma unroll
                for (int ni = 0; ni < 4; ni++)
                    MMA8(acc[mi][ni], af[mi], bf[ni]);
        }
        __syncthreads();
    }
    #pragma unroll
    for (int mi = 0; mi < 2; mi++)
        #pragma unroll
        for (int ni = 0; ni < 4; ni++)
            #pragma unroll
            for (int rg = 0; rg < 4; rg++) {
                int t = EPI_ROW(t0, wm, mi, rg);
                int d = EPI_COL(0, wn, ni, rg);
                g_ctx[((size_t)t * B_ + b) * E_ + h * D_ + d] = acc[mi][ni][rg];
            }
}

// ============================================================
// out projection
// ============================================================
__global__ __launch_bounds__(256) void k_out(const float* __restrict__ W,
                                             const float* __restrict__ bias,
                                             float* __restrict__ out) {
    float acc[4][4][4] = {};
    const int m0 = blockIdx.y * 128, n0 = blockIdx.x * 128;
    gemm_nt_main<E_, false>(g_ctx, E_, W, E_, m0, n0, nullptr, acc);
    const int lane = threadIdx.x & 31, warp = threadIdx.x >> 5;
    const int wm = (warp >> 2) * 64, wn = (warp & 3) * 32;
    #pragma unroll
    for (int mi = 0; mi < 4; mi++)
        #pragma unroll
        for (int ni = 0; ni < 4; ni++)
            #pragma unroll
            for (int rg = 0; rg < 4; rg++) {
                int row = EPI_ROW(m0, wm, mi, rg);
                int col = EPI_COL(n0, wn, ni, rg);
                out[(size_t)row * E_ + col] = acc[mi][ni][rg] + bias[col];
            }
}

// ============================================================
extern "C" void kernel_launch(void* const* d_in, const int* in_sizes, int n_in,
                              void* d_out, int out_size) {
    const float* input = (const float*)d_in[0];
    const float* pos   = (const float*)d_in[1];
    const float* w_in  = (const float*)d_in[2];
    const float* w_out = (const float*)d_in[3];
    const float* w_pos = (const float*)d_in[4];
    const float* b_in  = (const float*)d_in[5];
    const float* b_out = (const float*)d_in[6];
    const float* b_pos = (const float*)d_in[7];
    const float* rwb   = (const float*)d_in[8];
    const float* rrb   = (const float*)d_in[9];
    float* out = (float*)d_out;

    k_qkv  <<<dim3(E3_/128, (T_*B_)/128), 256>>>(input, w_in, b_in);
    k_pos  <<<dim3(E_/128,  T_/128),      256>>>(pos, w_pos, b_pos);
    k_score<<<dim3(T_/128, T_/128, 2*B_*H_), 256>>>(rwb, rrb);
    k_softmax<<<B_*H_*T_, 256>>>();
    k_av   <<<dim3(T_/128, B_*H_), 256>>>();
    k_out  <<<dim3(E_/128, (T_*B_)/128), 256>>>(w_out, b_out, out);
}

// round 3
// speedup vs baseline: 3.0200x; 1.3561x over previous
#include <cuda_runtime.h>
#include <math.h>

#define T_  2048
#define B_  2
#define E_  512
#define H_  8
#define D_  64
#define E3_ 1536

// scale * log2(e): softmax done in base-2 domain
#define SCL 0.1803368801111204f

// ---- scratch (__device__ globals: allocation-guard-legal) ----
__device__ float g_q[B_*H_*T_*D_];            // [B,H,T,D]
__device__ float g_k[B_*H_*T_*D_];
__device__ float g_v[B_*H_*T_*D_];
__device__ float g_r[H_*T_*D_];               // [H,R,D]
__device__ float g_BDs[(size_t)B_*H_*T_*T_];  // BD, PRE-SHIFTED + scaled
__device__ float g_ctx[T_*B_*E_];             // [T,B,E]

__device__ __forceinline__ unsigned f2tf32(float x) {
    unsigned r;
    asm("cvt.rna.tf32.f32 %0, %1;" : "=r"(r) : "f"(x));
    return r;
}

#define MMA8(d, a, b) \
  asm volatile("mma.sync.aligned.m16n8k8.row.col.f32.tf32.tf32.f32 " \
      "{%0,%1,%2,%3},{%4,%5,%6,%7},{%8,%9},{%0,%1,%2,%3};" \
      : "+f"((d)[0]), "+f"((d)[1]), "+f"((d)[2]), "+f"((d)[3]) \
      : "r"((a)[0]), "r"((a)[1]), "r"((a)[2]), "r"((a)[3]), \
        "r"((b)[0]), "r"((b)[1]))

// ============================================================
// Shared NT mainloop (as round 2): C[128,128] = A·Bt^T, K-contig.
// ============================================================
template<int KTOT, bool ABIAS>
__device__ __forceinline__ void gemm_nt_main(const float* __restrict__ A, int lda,
                                             const float* __restrict__ Bt, int ldb,
                                             int m0, int n0,
                                             const float* __restrict__ abias,
                                             float acc[4][4][4]) {
    __shared__ unsigned As[128][36];
    __shared__ unsigned Bs[128][36];
    const int tid = threadIdx.x;
    const int lane = tid & 31, warp = tid >> 5;
    const int wm = (warp >> 2) * 64, wn = (warp & 3) * 32;

    for (int k0 = 0; k0 < KTOT; k0 += 32) {
        #pragma unroll
        for (int i = 0; i < 4; i++) {
            int idx = tid + i * 256;
            int row = idx >> 3, c4 = (idx & 7) * 4;
            float4 va = *(const float4*)(A + (size_t)(m0 + row) * lda + k0 + c4);
            if (ABIAS) {
                va.x += abias[k0 + c4];     va.y += abias[k0 + c4 + 1];
                va.z += abias[k0 + c4 + 2]; va.w += abias[k0 + c4 + 3];
            }
            As[row][c4]   = f2tf32(va.x); As[row][c4+1] = f2tf32(va.y);
            As[row][c4+2] = f2tf32(va.z); As[row][c4+3] = f2tf32(va.w);
            float4 vb = *(const float4*)(Bt + (size_t)(n0 + row) * ldb + k0 + c4);
            Bs[row][c4]   = f2tf32(vb.x); Bs[row][c4+1] = f2tf32(vb.y);
            Bs[row][c4+2] = f2tf32(vb.z); Bs[row][c4+3] = f2tf32(vb.w);
        }
        __syncthreads();
        #pragma unroll
        for (int ks = 0; ks < 4; ks++) {
            const int kk = ks * 8;
            const int r = lane >> 2, c = kk + (lane & 3);
            unsigned af[4][4], bf[4][2];
            #pragma unroll
            for (int mi = 0; mi < 4; mi++) {
                int rr = wm + mi * 16 + r;
                af[mi][0] = As[rr][c];     af[mi][1] = As[rr + 8][c];
                af[mi][2] = As[rr][c + 4]; af[mi][3] = As[rr + 8][c + 4];
            }
            #pragma unroll
            for (int ni = 0; ni < 4; ni++) {
                int rb = wn + ni * 8 + r;
                bf[ni][0] = Bs[rb][c]; bf[ni][1] = Bs[rb][c + 4];
            }
            #pragma unroll
            for (int mi = 0; mi < 4; mi++)
                #pragma unroll
                for (int ni = 0; ni < 4; ni++)
                    MMA8(acc[mi][ni], af[mi], bf[ni]);
        }
        __syncthreads();
    }
}

#define EPI_ROW(m0, wm, mi, rg) ((m0) + (wm) + (mi)*16 + (lane >> 2) + (((rg) & 2) << 2))
#define EPI_COL(n0, wn, ni, rg) ((n0) + (wn) + (ni)*8 + ((lane & 3) << 1) + ((rg) & 1))

// ============================================================
// QKV projection -> q/k/v [B,H,T,D]
// ============================================================
__global__ __launch_bounds__(256) void k_qkv(const float* __restrict__ A,
                                             const float* __restrict__ W,
                                             const float* __restrict__ bias) {
    float acc[4][4][4] = {};
    const int m0 = blockIdx.y * 128, n0 = blockIdx.x * 128;
    gemm_nt_main<E_, false>(A, E_, W, E_, m0, n0, nullptr, acc);
    const int lane = threadIdx.x & 31, warp = threadIdx.x >> 5;
    const int wm = (warp >> 2) * 64, wn = (warp & 3) * 32;
    #pragma unroll
    for (int mi = 0; mi < 4; mi++)
        #pragma unroll
        for (int ni = 0; ni < 4; ni++)
            #pragma unroll
            for (int rg = 0; rg < 4; rg++) {
                int row = EPI_ROW(m0, wm, mi, rg);
                int col = EPI_COL(n0, wn, ni, rg);
                float v = acc[mi][ni][rg] + bias[col];
                int t = row / B_, b = row % B_;
                int sec = col >> 9, h = (col >> 6) & 7, d = col & 63;
                float* dst = (sec == 0) ? g_q : (sec == 1) ? g_k : g_v;
                dst[(((size_t)(b * H_ + h) * T_) + t) * D_ + d] = v;
            }
}

// ============================================================
// pos projection -> g_r[H,R,D]
// ============================================================
__global__ __launch_bounds__(256) void k_pos(const float* __restrict__ A,
                                             const float* __restrict__ W,
                                             const float* __restrict__ bias) {
    float acc[4][4][4] = {};
    const int m0 = blockIdx.y * 128, n0 = blockIdx.x * 128;
    gemm_nt_main<E_, false>(A, E_, W, E_, m0, n0, nullptr, acc);
    const int lane = threadIdx.x & 31, warp = threadIdx.x >> 5;
    const int wm = (warp >> 2) * 64, wn = (warp & 3) * 32;
    #pragma unroll
    for (int mi = 0; mi < 4; mi++)
        #pragma unroll
        for (int ni = 0; ni < 4; ni++)
            #pragma unroll
            for (int rg = 0; rg < 4; rg++) {
                int rr = EPI_ROW(m0, wm, mi, rg);
                int col = EPI_COL(n0, wn, ni, rg);
                int h = col >> 6, d = col & 63;
                g_r[((size_t)h * T_ + rr) * D_ + d] = acc[mi][ni][rg] + bias[col];
            }
}

// ============================================================
// BD: raw[t,c] = (q[t]+rrb)·r[c], scattered PRE-SHIFTED (bijection):
//   c >= T-1-t : target (t, c+t-(T-1))      [the s<=t region]
//   else (t>=1): target (t-1, c+t+1)        [the s>t+1 region]
// Slot (t, t+1) stays unwritten -> masked to 0 in k_flash.
// Scaled by SCL at write.
// ============================================================
__global__ __launch_bounds__(256) void k_bd(const float* __restrict__ rrb) {
    const int bh = blockIdx.z, h = bh & 7;
    const float* Aq = g_q + (size_t)bh * T_ * D_;
    const float* Bm = g_r + (size_t)h * T_ * D_;
    float* out = g_BDs + (size_t)bh * T_ * T_;
    const float* bias = rrb + h * D_;

    float acc[4][4][4] = {};
    const int m0 = blockIdx.y * 128, n0 = blockIdx.x * 128;
    gemm_nt_main<D_, true>(Aq, D_, Bm, D_, m0, n0, bias, acc);
    const int lane = threadIdx.x & 31, warp = threadIdx.x >> 5;
    const int wm = (warp >> 2) * 64, wn = (warp & 3) * 32;
    #pragma unroll
    for (int mi = 0; mi < 4; mi++)
        #pragma unroll
        for (int ni = 0; ni < 4; ni++)
            #pragma unroll
            for (int rg = 0; rg < 4; rg++) {
                int t = EPI_ROW(m0, wm, mi, rg);
                int c = EPI_COL(n0, wn, ni, rg);
                float v = acc[mi][ni][rg] * SCL;
                int s1 = c + t - (T_ - 1);
                if (s1 >= 0)
                    out[(size_t)t * T_ + s1] = v;
                else if (t >= 1)
                    out[(size_t)(t - 1) * T_ + (c + t + 1)] = v;
            }
}

// ============================================================
// Flash attention: per (t-tile 128, bh). Online softmax over s-tiles.
// Each warp owns 16 P-rows x 128 cols -> row stats reduce in lane quad.
// P round-trips through smem (C-layout -> A-layout) for P·V.
// ============================================================
__global__ __launch_bounds__(256, 1) void k_flash(const float* __restrict__ rwb) {
    extern __shared__ unsigned smem[];
    unsigned* Ks = smem;                 // [128][68]
    unsigned* Vs = Ks + 128 * 68;        // [128][72]
    unsigned* Ps = Vs + 128 * 72;        // [128][132]

    const int bh = blockIdx.y, h = bh & 7, b = bh >> 3;
    const int t0 = blockIdx.x * 128;
    const float* Q = g_q + (size_t)bh * T_ * D_;
    const float* K = g_k + (size_t)bh * T_ * D_;
    const float* V = g_v + (size_t)bh * T_ * D_;
    const float* BDs = g_BDs + (size_t)bh * T_ * T_;

    const int tid = threadIdx.x, lane = tid & 31, warp = tid >> 5;
    const int r = lane >> 2, cc = lane & 3;
    const int row0 = warp * 16;
    const int trow0 = t0 + row0 + r, trow1 = trow0 + 8;

    // q fragments, prescaled
    unsigned aq[8][4];
    const float* rwbh = rwb + h * D_;
    #pragma unroll
    for (int kc = 0; kc < 8; kc++) {
        int c0 = kc * 8 + cc;
        aq[kc][0] = f2tf32((Q[(size_t)trow0 * D_ + c0]     + rwbh[c0])     * SCL);
        aq[kc][1] = f2tf32((Q[(size_t)trow1 * D_ + c0]     + rwbh[c0])     * SCL);
        aq[kc][2] = f2tf32((Q[(size_t)trow0 * D_ + c0 + 4] + rwbh[c0 + 4]) * SCL);
        aq[kc][3] = f2tf32((Q[(size_t)trow1 * D_ + c0 + 4] + rwbh[c0 + 4]) * SCL);
    }

    float oacc[8][4] = {};
    float m0r = -1e30f, m1r = -1e30f, l0 = 0.f, l1 = 0.f;

    for (int s0 = 0; s0 < T_; s0 += 128) {
        // ---- stage K, V tiles ----
        #pragma unroll
        for (int i = 0; i < 8; i++) {
            int idx = tid + i * 256;
            int row = idx >> 4, c4 = (idx & 15) * 4;
            float4 kv = *(const float4*)(K + (size_t)(s0 + row) * D_ + c4);
            uint4 ku = { f2tf32(kv.x), f2tf32(kv.y), f2tf32(kv.z), f2tf32(kv.w) };
            *(uint4*)(Ks + row * 68 + c4) = ku;
            float4 vv = *(const float4*)(V + (size_t)(s0 + row) * D_ + c4);
            uint4 vu = { f2tf32(vv.x), f2tf32(vv.y), f2tf32(vv.z), f2tf32(vv.w) };
            *(uint4*)(Vs + row * 72 + c4) = vu;
        }
        __syncthreads();

        // ---- AC = qw · K^T ----
        float pacc[16][4];
        #pragma unroll
        for (int nt = 0; nt < 16; nt++)
            #pragma unroll
            for (int j = 0; j < 4; j++) pacc[nt][j] = 0.f;
        #pragma unroll
        for (int kc = 0; kc < 8; kc++) {
            #pragma unroll
            for (int nt = 0; nt < 16; nt++) {
                unsigned bf[2];
                int srow = nt * 8 + r;
                bf[0] = Ks[srow * 68 + kc * 8 + cc];
                bf[1] = Ks[srow * 68 + kc * 8 + cc + 4];
                MMA8(pacc[nt], aq[kc], bf);
            }
        }

        // ---- add pre-shifted BD (mask s==t+1), row max ----
        float pm0 = -1e30f, pm1 = -1e30f;
        #pragma unroll
        for (int nt = 0; nt < 16; nt++) {
            int sb = s0 + nt * 8 + 2 * cc;
            float2 b0 = *(const float2*)(BDs + (size_t)trow0 * T_ + sb);
            float2 b1 = *(const float2*)(BDs + (size_t)trow1 * T_ + sb);
            pacc[nt][0] += (sb     == trow0 + 1) ? 0.f : b0.x;
            pacc[nt][1] += (sb + 1 == trow0 + 1) ? 0.f : b0.y;
            pacc[nt][2] += (sb     == trow1 + 1) ? 0.f : b1.x;
            pacc[nt][3] += (sb + 1 == trow1 + 1) ? 0.f : b1.y;
            pm0 = fmaxf(pm0, fmaxf(pacc[nt][0], pacc[nt][1]));
            pm1 = fmaxf(pm1, fmaxf(pacc[nt][2], pacc[nt][3]));
        }
        pm0 = fmaxf(pm0, __shfl_xor_sync(0xffffffffu, pm0, 1));
        pm0 = fmaxf(pm0, __shfl_xor_sync(0xffffffffu, pm0, 2));
        pm1 = fmaxf(pm1, __shfl_xor_sync(0xffffffffu, pm1, 1));
        pm1 = fmaxf(pm1, __shfl_xor_sync(0xffffffffu, pm1, 2));

        float mn0 = fmaxf(m0r, pm0), mn1 = fmaxf(m1r, pm1);
        float sf0 = exp2f(m0r - mn0), sf1 = exp2f(m1r - mn1);
        m0r = mn0; m1r = mn1;
        #pragma unroll
        for (int nt = 0; nt < 8; nt++) {
            oacc[nt][0] *= sf0; oacc[nt][1] *= sf0;
            oacc[nt][2] *= sf1; oacc[nt][3] *= sf1;
        }
        l0 *= sf0; l1 *= sf1;

        // ---- exp, rowsum, store P (A-layout smem) ----
        float sum0 = 0.f, sum1 = 0.f;
        #pragma unroll
        for (int nt = 0; nt < 16; nt++) {
            float e0 = exp2f(pacc[nt][0] - mn0);
            float e1 = exp2f(pacc[nt][1] - mn0);
            float e2 = exp2f(pacc[nt][2] - mn1);
            float e3 = exp2f(pacc[nt][3] - mn1);
            sum0 += e0 + e1; sum1 += e2 + e3;
            int col = nt * 8 + 2 * cc;
            Ps[(row0 + r) * 132 + col]     = f2tf32(e0);
            Ps[(row0 + r) * 132 + col + 1] = f2tf32(e1);
            Ps[(row0 + r + 8) * 132 + col]     = f2tf32(e2);
            Ps[(row0 + r + 8) * 132 + col + 1] = f2tf32(e3);
        }
        sum0 += __shfl_xor_sync(0xffffffffu, sum0, 1);
        sum0 += __shfl_xor_sync(0xffffffffu, sum0, 2);
        sum1 += __shfl_xor_sync(0xffffffffu, sum1, 1);
        sum1 += __shfl_xor_sync(0xffffffffu, sum1, 2);
        l0 += sum0; l1 += sum1;

        __syncwarp();

        // ---- O += P · V ----
        #pragma unroll
        for (int kc = 0; kc < 16; kc++) {
            unsigned af[4];
            af[0] = Ps[(row0 + r) * 132 + kc * 8 + cc];
            af[1] = Ps[(row0 + r + 8) * 132 + kc * 8 + cc];
            af[2] = Ps[(row0 + r) * 132 + kc * 8 + cc + 4];
            af[3] = Ps[(row0 + r + 8) * 132 + kc * 8 + cc + 4];
            #pragma unroll
            for (int nt = 0; nt < 8; nt++) {
                unsigned bf[2];
                bf[0] = Vs[(kc * 8 + cc) * 72 + nt * 8 + r];
                bf[1] = Vs[(kc * 8 + cc + 4) * 72 + nt * 8 + r];
                MMA8(oacc[nt], af, bf);
            }
        }
        __syncthreads();
    }

    // ---- epilogue: O /= l -> g_ctx[t, b, h*64+d] ----
    float il0 = 1.f / l0, il1 = 1.f / l1;
    #pragma unroll
    for (int nt = 0; nt < 8; nt++) {
        int d = h * 64 + nt * 8 + 2 * cc;
        float2 o0 = { oacc[nt][0] * il0, oacc[nt][1] * il0 };
        *(float2*)(g_ctx + ((size_t)trow0 * B_ + b) * E_ + d) = o0;
        float2 o1 = { oacc[nt][2] * il1, oacc[nt][3] * il1 };
        *(float2*)(g_ctx + ((size_t)trow1 * B_ + b) * E_ + d) = o1;
    }
}

// ============================================================
// out projection
// ============================================================
__global__ __launch_bounds__(256) void k_out(const float* __restrict__ W,
                                             const float* __restrict__ bias,
                                             float* __restrict__ out) {
    float acc[4][4][4] = {};
    const int m0 = blockIdx.y * 128, n0 = blockIdx.x * 128;
    gemm_nt_main<E_, false>(g_ctx, E_, W, E_, m0, n0, nullptr, acc);
    const int lane = threadIdx.x & 31, warp = threadIdx.x >> 5;
    const int wm = (warp >> 2) * 64, wn = (warp & 3) * 32;
    #pragma unroll
    for (int mi = 0; mi < 4; mi++)
        #pragma unroll
        for (int ni = 0; ni < 4; ni++)
            #pragma unroll
            for (int rg = 0; rg < 4; rg++) {
                int row = EPI_ROW(m0, wm, mi, rg);
                int col = EPI_COL(n0, wn, ni, rg);
                out[(size_t)row * E_ + col] = acc[mi][ni][rg] + bias[col];
            }
}

// ============================================================
extern "C" void kernel_launch(void* const* d_in, const int* in_sizes, int n_in,
                              void* d_out, int out_size) {
    const float* input = (const float*)d_in[0];
    const float* pos   = (const float*)d_in[1];
    const float* w_in  = (const float*)d_in[2];
    const float* w_out = (const float*)d_in[3];
    const float* w_pos = (const float*)d_in[4];
    const float* b_in  = (const float*)d_in[5];
    const float* b_out = (const float*)d_in[6];
    const float* b_pos = (const float*)d_in[7];
    const float* rwb   = (const float*)d_in[8];
    const float* rrb   = (const float*)d_in[9];
    float* out = (float*)d_out;

    const int flash_smem = (128 * 68 + 128 * 72 + 128 * 132) * 4;  // 139264 B
    static int configured = 0;
    if (!configured) {
        cudaFuncSetAttribute(k_flash, cudaFuncAttributeMaxDynamicSharedMemorySize,
                             flash_smem);
        configured = 1;
    }

    k_qkv <<<dim3(E3_/128, (T_*B_)/128), 256>>>(input, w_in, b_in);
    k_pos <<<dim3(E_/128,  T_/128),      256>>>(pos, w_pos, b_pos);
    k_bd  <<<dim3(T_/128, T_/128, B_*H_), 256>>>(rrb);
    k_flash<<<dim3(T_/128, B_*H_), 256, flash_smem>>>(rwb);
    k_out <<<dim3(E_/128, (T_*B_)/128), 256>>>(w_out, b_out, out);
}

// round 4
// speedup vs baseline: 3.1483x; 1.0425x over previous
#include <cuda_runtime.h>
#include <cuda_fp16.h>
#include <math.h>

#define T_  2048
#define B_  2
#define E_  512
#define H_  8
#define D_  64
#define E3_ 1536

// scale * log2(e): softmax in base-2 domain
#define SCL 0.1803368801111204f

// ---- scratch (__device__ globals: allocation-guard-legal) ----
__device__ float g_q[B_*H_*T_*D_];            // [B,H,T,D] fp32
__device__ float g_k[B_*H_*T_*D_];            // [B,H,T,D] tf32-bits
__device__ float g_v[B_*H_*T_*D_];            // [B,H,T,D] tf32-bits
__device__ float g_r[H_*T_*D_];               // [H,R,D]
__device__ __half g_BDs[(size_t)B_*H_*T_*T_]; // BD, PRE-SHIFTED + scaled, fp16
__device__ float g_ctx[T_*B_*E_];             // [T,B,E]

__device__ __forceinline__ unsigned f2tf32(float x) {
    unsigned r;
    asm("cvt.rna.tf32.f32 %0, %1;" : "=r"(r) : "f"(x));
    return r;
}
__device__ __forceinline__ float ex2f(float x) {
    float y;
    asm("ex2.approx.ftz.f32 %0, %1;" : "=f"(y) : "f"(x));
    return y;
}
__device__ __forceinline__ void cpa16(void* d, const void* s) {
    unsigned a = (unsigned)__cvta_generic_to_shared(d);
    asm volatile("cp.async.cg.shared.global [%0], [%1], 16;" :: "r"(a), "l"(s));
}

#define MMA8(d, a, b) \
  asm volatile("mma.sync.aligned.m16n8k8.row.col.f32.tf32.tf32.f32 " \
      "{%0,%1,%2,%3},{%4,%5,%6,%7},{%8,%9},{%0,%1,%2,%3};" \
      : "+f"((d)[0]), "+f"((d)[1]), "+f"((d)[2]), "+f"((d)[3]) \
      : "r"((a)[0]), "r"((a)[1]), "r"((a)[2]), "r"((a)[3]), \
        "r"((b)[0]), "r"((b)[1]))

// ============================================================
// Shared NT mainloop: C[128,128] = A·Bt^T, K-contig operands.
// ============================================================
template<int KTOT, bool ABIAS>
__device__ __forceinline__ void gemm_nt_main(const float* __restrict__ A, int lda,
                                             const float* __restrict__ Bt, int ldb,
                                             int m0, int n0,
                                             const float* __restrict__ abias,
                                             float acc[4][4][4]) {
    __shared__ unsigned As[128][36];
    __shared__ unsigned Bs[128][36];
    const int tid = threadIdx.x;
    const int lane = tid & 31, warp = tid >> 5;
    const int wm = (warp >> 2) * 64, wn = (warp & 3) * 32;

    for (int k0 = 0; k0 < KTOT; k0 += 32) {
        #pragma unroll
        for (int i = 0; i < 4; i++) {
            int idx = tid + i * 256;
            int row = idx >> 3, c4 = (idx & 7) * 4;
            float4 va = *(const float4*)(A + (size_t)(m0 + row) * lda + k0 + c4);
            if (ABIAS) {
                va.x += abias[k0 + c4];     va.y += abias[k0 + c4 + 1];
                va.z += abias[k0 + c4 + 2]; va.w += abias[k0 + c4 + 3];
            }
            As[row][c4]   = f2tf32(va.x); As[row][c4+1] = f2tf32(va.y);
            As[row][c4+2] = f2tf32(va.z); As[row][c4+3] = f2tf32(va.w);
            float4 vb = *(const float4*)(Bt + (size_t)(n0 + row) * ldb + k0 + c4);
            Bs[row][c4]   = f2tf32(vb.x); Bs[row][c4+1] = f2tf32(vb.y);
            Bs[row][c4+2] = f2tf32(vb.z); Bs[row][c4+3] = f2tf32(vb.w);
        }
        __syncthreads();
        #pragma unroll
        for (int ks = 0; ks < 4; ks++) {
            const int kk = ks * 8;
            const int r = lane >> 2, c = kk + (lane & 3);
            unsigned af[4][4], bf[4][2];
            #pragma unroll
            for (int mi = 0; mi < 4; mi++) {
                int rr = wm + mi * 16 + r;
                af[mi][0] = As[rr][c];     af[mi][1] = As[rr + 8][c];
                af[mi][2] = As[rr][c + 4]; af[mi][3] = As[rr + 8][c + 4];
            }
            #pragma unroll
            for (int ni = 0; ni < 4; ni++) {
                int rb = wn + ni * 8 + r;
                bf[ni][0] = Bs[rb][c]; bf[ni][1] = Bs[rb][c + 4];
            }
            #pragma unroll
            for (int mi = 0; mi < 4; mi++)
                #pragma unroll
                for (int ni = 0; ni < 4; ni++)
                    MMA8(acc[mi][ni], af[mi], bf[ni]);
        }
        __syncthreads();
    }
}

#define EPI_ROW(m0, wm, mi, rg) ((m0) + (wm) + (mi)*16 + (lane >> 2) + (((rg) & 2) << 2))
#define EPI_COL(n0, wn, ni, rg) ((n0) + (wn) + (ni)*8 + ((lane & 3) << 1) + ((rg) & 1))

// ============================================================
// QKV projection -> q (fp32), k/v (tf32-bit floats) [B,H,T,D]
// ============================================================
__global__ __launch_bounds__(256) void k_qkv(const float* __restrict__ A,
                                             const float* __restrict__ W,
                                             const float* __restrict__ bias) {
    float acc[4][4][4] = {};
    const int m0 = blockIdx.y * 128, n0 = blockIdx.x * 128;
    gemm_nt_main<E_, false>(A, E_, W, E_, m0, n0, nullptr, acc);
    const int lane = threadIdx.x & 31, warp = threadIdx.x >> 5;
    const int wm = (warp >> 2) * 64, wn = (warp & 3) * 32;
    #pragma unroll
    for (int mi = 0; mi < 4; mi++)
        #pragma unroll
        for (int ni = 0; ni < 4; ni++)
            #pragma unroll
            for (int rg = 0; rg < 4; rg++) {
                int row = EPI_ROW(m0, wm, mi, rg);
                int col = EPI_COL(n0, wn, ni, rg);
                float v = acc[mi][ni][rg] + bias[col];
                int t = row / B_, b = row % B_;
                int sec = col >> 9, h = (col >> 6) & 7, d = col & 63;
                float* dst = (sec == 0) ? g_q : (sec == 1) ? g_k : g_v;
                if (sec != 0) v = __uint_as_float(f2tf32(v));   // pre-convert K,V
                dst[(((size_t)(b * H_ + h) * T_) + t) * D_ + d] = v;
            }
}

// ============================================================
// pos projection -> g_r[H,R,D]
// ============================================================
__global__ __launch_bounds__(256) void k_pos(const float* __restrict__ A,
                                             const float* __restrict__ W,
                                             const float* __restrict__ bias) {
    float acc[4][4][4] = {};
    const int m0 = blockIdx.y * 128, n0 = blockIdx.x * 128;
    gemm_nt_main<E_, false>(A, E_, W, E_, m0, n0, nullptr, acc);
    const int lane = threadIdx.x & 31, warp = threadIdx.x >> 5;
    const int wm = (warp >> 2) * 64, wn = (warp & 3) * 32;
    #pragma unroll
    for (int mi = 0; mi < 4; mi++)
        #pragma unroll
        for (int ni = 0; ni < 4; ni++)
            #pragma unroll
            for (int rg = 0; rg < 4; rg++) {
                int rr = EPI_ROW(m0, wm, mi, rg);
                int col = EPI_COL(n0, wn, ni, rg);
                int h = col >> 6, d = col & 63;
                g_r[((size_t)h * T_ + rr) * D_ + d] = acc[mi][ni][rg] + bias[col];
            }
}

// ============================================================
// BD: raw[t,c] = (q[t]+rrb)·r[c], scattered PRE-SHIFTED + scaled, fp16:
//   c >= T-1-t : (t, c+t-(T-1));  else (t>=1): (t-1, c+t+1)
// Slot (t,t+1) unwritten -> masked in k_flash.
// ============================================================
__global__ __launch_bounds__(256) void k_bd(const float* __restrict__ rrb) {
    const int bh = blockIdx.z, h = bh & 7;
    const float* Aq = g_q + (size_t)bh * T_ * D_;
    const float* Bm = g_r + (size_t)h * T_ * D_;
    __half* out = g_BDs + (size_t)bh * T_ * T_;
    const float* bias = rrb + h * D_;

    float acc[4][4][4] = {};
    const int m0 = blockIdx.y * 128, n0 = blockIdx.x * 128;
    gemm_nt_main<D_, true>(Aq, D_, Bm, D_, m0, n0, bias, acc);
    const int lane = threadIdx.x & 31, warp = threadIdx.x >> 5;
    const int wm = (warp >> 2) * 64, wn = (warp & 3) * 32;
    #pragma unroll
    for (int mi = 0; mi < 4; mi++)
        #pragma unroll
        for (int ni = 0; ni < 4; ni++)
            #pragma unroll
            for (int rg = 0; rg < 4; rg++) {
                int t = EPI_ROW(m0, wm, mi, rg);
                int c = EPI_COL(n0, wn, ni, rg);
                __half v = __float2half_rn(acc[mi][ni][rg] * SCL);
                int s1 = c + t - (T_ - 1);
                if (s1 >= 0)
                    out[(size_t)t * T_ + s1] = v;
                else if (t >= 1)
                    out[(size_t)(t - 1) * T_ + (c + t + 1)] = v;
            }
}

// ============================================================
// Flash attention, fully pipelined:
//  - K/V (pre-tf32) cp.async double-buffered, 1 tile ahead
//  - BD (fp16) cp.async'd into Ps buffer 1 tile ahead; consumed into
//    pacc, then Ps overwritten in place with tf32 P (warp-local rows)
//  - one __syncthreads per s-tile
// ============================================================
__global__ __launch_bounds__(256, 1) void k_flash(const float* __restrict__ rwb) {
    extern __shared__ unsigned smem[];
    const int BUFW = 128*68 + 128*72;      // words per KV buffer
    unsigned* Ps = smem + 2 * BUFW;        // [128][132] words; BD lands in words 0..63/row

    const int bh = blockIdx.y, h = bh & 7, b = bh >> 3;
    const int t0 = blockIdx.x * 128;
    const float*  Q  = g_q + (size_t)bh * T_ * D_;
    const float*  K  = g_k + (size_t)bh * T_ * D_;
    const float*  V  = g_v + (size_t)bh * T_ * D_;
    const __half* BD = g_BDs + (size_t)bh * T_ * T_;

    const int tid = threadIdx.x, lane = tid & 31, warp = tid >> 5;
    const int r = lane >> 2, cc = lane & 3;
    const int row0 = warp * 16;
    const int trow0 = t0 + row0 + r, trow1 = trow0 + 8;

#define PREFETCH_KV(buf, s0_) do {                                            \
    unsigned* Kb_ = smem + (buf) * BUFW;                                      \
    unsigned* Vb_ = Kb_ + 128*68;                                             \
    _Pragma("unroll")                                                         \
    for (int i_ = 0; i_ < 8; i_++) {                                          \
        int idx_ = tid + i_ * 256;                                            \
        int row_ = idx_ >> 4, c4_ = (idx_ & 15) * 4;                          \
        cpa16(Kb_ + row_*68 + c4_, K + (size_t)((s0_) + row_) * D_ + c4_);    \
        cpa16(Vb_ + row_*72 + c4_, V + (size_t)((s0_) + row_) * D_ + c4_);    \
    }                                                                         \
    asm volatile("cp.async.commit_group;" ::: "memory");                      \
} while (0)

#define PREFETCH_BD(s0_) do {                                                 \
    _Pragma("unroll")                                                         \
    for (int i_ = 0; i_ < 8; i_++) {                                          \
        int idx_ = lane + i_ * 32;                                            \
        int row_ = idx_ >> 4, c16_ = idx_ & 15;                               \
        cpa16(Ps + (row0 + row_) * 132 + c16_ * 4,                            \
              BD + (size_t)(t0 + row0 + row_) * T_ + (s0_) + c16_ * 8);       \
    }                                                                         \
    asm volatile("cp.async.commit_group;" ::: "memory");                      \
} while (0)

    // q fragments, prescaled (fp32 -> rna tf32)
    unsigned aq[8][4];
    const float* rwbh = rwb + h * D_;
    #pragma unroll
    for (int kc = 0; kc < 8; kc++) {
        int c0 = kc * 8 + cc;
        aq[kc][0] = f2tf32((Q[(size_t)trow0 * D_ + c0]     + rwbh[c0])     * SCL);
        aq[kc][1] = f2tf32((Q[(size_t)trow1 * D_ + c0]     + rwbh[c0])     * SCL);
        aq[kc][2] = f2tf32((Q[(size_t)trow0 * D_ + c0 + 4] + rwbh[c0 + 4]) * SCL);
        aq[kc][3] = f2tf32((Q[(size_t)trow1 * D_ + c0 + 4] + rwbh[c0 + 4]) * SCL);
    }

    PREFETCH_KV(0, 0);   // group: KV(0)
    PREFETCH_BD(0);      // group: BD(0)

    float oacc[8][4] = {};
    float m0r = -1e30f, m1r = -1e30f, l0 = 0.f, l1 = 0.f;

    #pragma unroll 1
    for (int it = 0; it < T_ / 128; it++) {
        const int s0 = it * 128;
        const int cur = it & 1;
        // outstanding: {KV(it), BD(it)} -> wait KV(it)
        asm volatile("cp.async.wait_group 1;" ::: "memory");
        __syncthreads();

        PREFETCH_KV(cur ^ 1, (s0 + 128) & (T_ - 1));   // +{KV(it+1)}

        const unsigned* Kb = smem + cur * BUFW;
        const unsigned* Vb = Kb + 128*68;

        // ---- AC = qw · K^T ----
        float pacc[16][4];
        #pragma unroll
        for (int nt = 0; nt < 16; nt++)
            #pragma unroll
            for (int j = 0; j < 4; j++) pacc[nt][j] = 0.f;
        #pragma unroll
        for (int kc = 0; kc < 8; kc++) {
            #pragma unroll
            for (int nt = 0; nt < 16; nt++) {
                unsigned bf[2];
                int srow = nt * 8 + r;
                bf[0] = Kb[srow * 68 + kc * 8 + cc];
                bf[1] = Kb[srow * 68 + kc * 8 + cc + 4];
                MMA8(pacc[nt], aq[kc], bf);
            }
        }

        // ---- BD(it) is second-oldest outstanding group -> wait to depth 1
        asm volatile("cp.async.wait_group 1;" ::: "memory");
        __syncwarp();   // join lanes' private groups (BD rows are warp-local)

        // ---- add BD from Ps (mask s==t+1), row max ----
        const __half2* bd0 = (const __half2*)(Ps + (row0 + r) * 132);
        const __half2* bd1 = (const __half2*)(Ps + (row0 + r + 8) * 132);
        float pm0 = -1e30f, pm1 = -1e30f;
        #pragma unroll
        for (int nt = 0; nt < 16; nt++) {
            int sb = s0 + nt * 8 + 2 * cc;
            float2 f0 = __half22float2(bd0[4 * nt + cc]);
            float2 f1 = __half22float2(bd1[4 * nt + cc]);
            pacc[nt][0] += (sb     == trow0 + 1) ? 0.f : f0.x;
            pacc[nt][1] += (sb + 1 == trow0 + 1) ? 0.f : f0.y;
            pacc[nt][2] += (sb     == trow1 + 1) ? 0.f : f1.x;
            pacc[nt][3] += (sb + 1 == trow1 + 1) ? 0.f : f1.y;
            pm0 = fmaxf(pm0, fmaxf(pacc[nt][0], pacc[nt][1]));
            pm1 = fmaxf(pm1, fmaxf(pacc[nt][2], pacc[nt][3]));
        }
        pm0 = fmaxf(pm0, __shfl_xor_sync(0xffffffffu, pm0, 1));
        pm0 = fmaxf(pm0, __shfl_xor_sync(0xffffffffu, pm0, 2));
        pm1 = fmaxf(pm1, __shfl_xor_sync(0xffffffffu, pm1, 1));
        pm1 = fmaxf(pm1, __shfl_xor_sync(0xffffffffu, pm1, 2));
        // shuffles converge the warp: all BD reads done before P overwrites

        float mn0 = fmaxf(m0r, pm0), mn1 = fmaxf(m1r, pm1);
        float sf0 = ex2f(m0r - mn0), sf1 = ex2f(m1r - mn1);
        m0r = mn0; m1r = mn1;
        #pragma unroll
        for (int nt = 0; nt < 8; nt++) {
            oacc[nt][0] *= sf0; oacc[nt][1] *= sf0;
            oacc[nt][2] *= sf1; oacc[nt][3] *= sf1;
        }
        l0 *= sf0; l1 *= sf1;

        // ---- exp, rowsum, store P in place over BD (A-layout) ----
        float sum0 = 0.f, sum1 = 0.f;
        #pragma unroll
        for (int nt = 0; nt < 16; nt++) {
            float e0 = ex2f(pacc[nt][0] - mn0);
            float e1 = ex2f(pacc[nt][1] - mn0);
            float e2 = ex2f(pacc[nt][2] - mn1);
            float e3 = ex2f(pacc[nt][3] - mn1);
            sum0 += e0 + e1; sum1 += e2 + e3;
            int col = nt * 8 + 2 * cc;
            uint2 p0 = { f2tf32(e0), f2tf32(e1) };
            *(uint2*)(Ps + (row0 + r) * 132 + col) = p0;
            uint2 p1 = { f2tf32(e2), f2tf32(e3) };
            *(uint2*)(Ps + (row0 + r + 8) * 132 + col) = p1;
        }
        sum0 += __shfl_xor_sync(0xffffffffu, sum0, 1);
        sum0 += __shfl_xor_sync(0xffffffffu, sum0, 2);
        sum1 += __shfl_xor_sync(0xffffffffu, sum1, 1);
        sum1 += __shfl_xor_sync(0xffffffffu, sum1, 2);
        l0 += sum0; l1 += sum1;

        __syncwarp();

        // ---- O += P · V ----
        #pragma unroll
        for (int kc = 0; kc < 16; kc++) {
            unsigned af[4];
            af[0] = Ps[(row0 + r) * 132 + kc * 8 + cc];
            af[1] = Ps[(row0 + r + 8) * 132 + kc * 8 + cc];
            af[2] = Ps[(row0 + r) * 132 + kc * 8 + cc + 4];
            af[3] = Ps[(row0 + r + 8) * 132 + kc * 8 + cc + 4];
            #pragma unroll
            for (int nt = 0; nt < 8; nt++) {
                unsigned bf[2];
                bf[0] = Vb[(kc * 8 + cc) * 72 + nt * 8 + r];
                bf[1] = Vb[(kc * 8 + cc + 4) * 72 + nt * 8 + r];
                MMA8(oacc[nt], af, bf);
            }
        }
        __syncwarp();

        if (it < T_ / 128 - 1)
            PREFETCH_BD(s0 + 128);   // lands over Ps after this tile's PV reads
    }
    asm volatile("cp.async.wait_group 0;" ::: "memory");  // drain dummy KV

    // ---- epilogue: O /= l -> g_ctx[t, b, h*64+d] ----
    float il0 = 1.f / l0, il1 = 1.f / l1;
    #pragma unroll
    for (int nt = 0; nt < 8; nt++) {
        int d = h * 64 + nt * 8 + 2 * cc;
        float2 o0 = { oacc[nt][0] * il0, oacc[nt][1] * il0 };
        *(float2*)(g_ctx + ((size_t)trow0 * B_ + b) * E_ + d) = o0;
        float2 o1 = { oacc[nt][2] * il1, oacc[nt][3] * il1 };
        *(float2*)(g_ctx + ((size_t)trow1 * B_ + b) * E_ + d) = o1;
    }
#undef PREFETCH_KV
#undef PREFETCH_BD
}

// ============================================================
// out projection
// ============================================================
__global__ __launch_bounds__(256) void k_out(const float* __restrict__ W,
                                             const float* __restrict__ bias,
                                             float* __restrict__ out) {
    float acc[4][4][4] = {};
    const int m0 = blockIdx.y * 128, n0 = blockIdx.x * 128;
    gemm_nt_main<E_, false>(g_ctx, E_, W, E_, m0, n0, nullptr, acc);
    const int lane = threadIdx.x & 31, warp = threadIdx.x >> 5;
    const int wm = (warp >> 2) * 64, wn = (warp & 3) * 32;
    #pragma unroll
    for (int mi = 0; mi < 4; mi++)
        #pragma unroll
        for (int ni = 0; ni < 4; ni++)
            #pragma unroll
            for (int rg = 0; rg < 4; rg++) {
                int row = EPI_ROW(m0, wm, mi, rg);
                int col = EPI_COL(n0, wn, ni, rg);
                out[(size_t)row * E_ + col] = acc[mi][ni][rg] + bias[col];
            }
}

// ============================================================
extern "C" void kernel_launch(void* const* d_in, const int* in_sizes, int n_in,
                              void* d_out, int out_size) {
    const float* input = (const float*)d_in[0];
    const float* pos   = (const float*)d_in[1];
    const float* w_in  = (const float*)d_in[2];
    const float* w_out = (const float*)d_in[3];
    const float* w_pos = (const float*)d_in[4];
    const float* b_in  = (const float*)d_in[5];
    const float* b_out = (const float*)d_in[6];
    const float* b_pos = (const float*)d_in[7];
    const float* rwb   = (const float*)d_in[8];
    const float* rrb   = (const float*)d_in[9];
    float* out = (float*)d_out;

    const int flash_smem = (2 * (128*68 + 128*72) + 128*132) * 4;  // 210944 B
    cudaFuncSetAttribute(k_flash, cudaFuncAttributeMaxDynamicSharedMemorySize,
                         flash_smem);

    k_qkv <<<dim3(E3_/128, (T_*B_)/128), 256>>>(input, w_in, b_in);
    k_pos <<<dim3(E_/128,  T_/128),      256>>>(pos, w_pos, b_pos);
    k_bd  <<<dim3(T_/128, T_/128, B_*H_), 256>>>(rrb);
    k_flash<<<dim3(T_/128, B_*H_), 256, flash_smem>>>(rwb);
    k_out <<<dim3(E_/128, (T_*B_)/128), 256>>>(w_out, b_out, out);
}

// round 5
// speedup vs baseline: 4.0623x; 1.2903x over previous
#include <cuda_runtime.h>
#include <cuda_fp16.h>
#include <math.h>

#define T_  2048
#define B_  2
#define E_  512
#define H_  8
#define D_  64
#define E3_ 1536

// scale * log2(e): softmax in base-2 domain
#define SCL 0.1803368801111204f

// ---- scratch (__device__ globals: allocation-guard-legal) ----
__device__ float g_q[B_*H_*T_*D_];            // [B,H,T,D] tf32-bits
__device__ float g_k[B_*H_*T_*D_];            // [B,H,T,D] tf32-bits, d-permuted
__device__ float g_v[B_*H_*T_*D_];            // [B,H,T,D] tf32-bits
__device__ float g_r[H_*T_*D_];               // [H,R,D]   tf32-bits
__device__ float g_br[H_*T_];                 // rrb_h · r[h,c]
__device__ __half g_BDs[(size_t)B_*H_*T_*T_]; // BD, PRE-SHIFTED + scaled, fp16
__device__ float g_ctx[T_*B_*E_];             // [T,B,E]   tf32-bits
// tf32-rounded copies of harness inputs (enables raw cp.async GEMMs)
__device__ float g_ci[T_*B_*E_];
__device__ float g_cpos[T_*E_];
__device__ float g_cwin[E3_*E_];
__device__ float g_cwout[E_*E_];
__device__ float g_cwpos[E_*E_];

__device__ __forceinline__ unsigned f2tf32(float x) {
    unsigned r;
    asm("cvt.rna.tf32.f32 %0, %1;" : "=r"(r) : "f"(x));
    return r;
}
__device__ __forceinline__ float ex2f(float x) {
    float y;
    asm("ex2.approx.ftz.f32 %0, %1;" : "=f"(y) : "f"(x));
    return y;
}
__device__ __forceinline__ void cpa16(void* d, const void* s) {
    unsigned a = (unsigned)__cvta_generic_to_shared(d);
    asm volatile("cp.async.cg.shared.global [%0], [%1], 16;" :: "r"(a), "l"(s));
}

#define MMA8(d, a, b) \
  asm volatile("mma.sync.aligned.m16n8k8.row.col.f32.tf32.tf32.f32 " \
      "{%0,%1,%2,%3},{%4,%5,%6,%7},{%8,%9},{%0,%1,%2,%3};" \
      : "+f"((d)[0]), "+f"((d)[1]), "+f"((d)[2]), "+f"((d)[3]) \
      : "r"((a)[0]), "r"((a)[1]), "r"((a)[2]), "r"((a)[3]), \
        "r"((b)[0]), "r"((b)[1]))

// ============================================================
// tf32-rounding copy kernel (vec4)
// ============================================================
__global__ __launch_bounds__(256) void k_cvt(float* __restrict__ dst,
                                             const float* __restrict__ src, int n4) {
    int i = blockIdx.x * 256 + threadIdx.x;
    if (i < n4) {
        float4 v = ((const float4*)src)[i];
        uint4 u = { f2tf32(v.x), f2tf32(v.y), f2tf32(v.z), f2tf32(v.w) };
        ((uint4*)dst)[i] = u;
    }
}

// ============================================================
// Double-buffered cp.async NT mainloop: C[128,128] = A·Bt^T.
// Operands MUST be pre-rounded tf32 bits (raw bytes -> MMA).
// Dynamic smem: 2 stages x (As[128][36] + Bs[128][36]) = 73728 B.
// ============================================================
template<int KTOT>
__device__ __forceinline__ void gemm_nt_cp(const float* __restrict__ A, int lda,
                                           const float* __restrict__ Bt, int ldb,
                                           int m0, int n0, float acc[4][4][4],
                                           unsigned* sm) {
    const int tid = threadIdx.x;
    const int lane = tid & 31, warp = tid >> 5;
    const int wm = (warp >> 2) * 64, wn = (warp & 3) * 32;

#define GSTAGE(buf_, k0_) do {                                                \
    unsigned* As_ = sm + (buf_) * 9216;                                       \
    unsigned* Bs_ = As_ + 4608;                                               \
    _Pragma("unroll")                                                         \
    for (int i_ = 0; i_ < 4; i_++) {                                          \
        int idx_ = tid + i_ * 256;                                            \
        int row_ = idx_ >> 3, c4_ = (idx_ & 7) * 4;                           \
        cpa16(As_ + row_*36 + c4_, A  + (size_t)(m0 + row_) * lda + (k0_) + c4_); \
        cpa16(Bs_ + row_*36 + c4_, Bt + (size_t)(n0 + row_) * ldb + (k0_) + c4_); \
    }                                                                         \
    asm volatile("cp.async.commit_group;" ::: "memory");                      \
} while (0)

    GSTAGE(0, 0);
    #pragma unroll 1
    for (int k0 = 0; k0 < KTOT; k0 += 32) {
        const int buf = (k0 >> 5) & 1;
        const bool more = (k0 + 32 < KTOT);
        if (more) GSTAGE(buf ^ 1, k0 + 32);
        if (more) asm volatile("cp.async.wait_group 1;" ::: "memory");
        else      asm volatile("cp.async.wait_group 0;" ::: "memory");
        __syncthreads();

        const unsigned* As = sm + buf * 9216;
        const unsigned* Bs = As + 4608;
        #pragma unroll
        for (int ks = 0; ks < 4; ks++) {
            const int kk = ks * 8;
            const int r = lane >> 2, c = kk + (lane & 3);
            unsigned af[4][4], bf[4][2];
            #pragma unroll
            for (int mi = 0; mi < 4; mi++) {
                int rr = wm + mi * 16 + r;
                af[mi][0] = As[rr*36 + c];     af[mi][1] = As[(rr+8)*36 + c];
                af[mi][2] = As[rr*36 + c + 4]; af[mi][3] = As[(rr+8)*36 + c + 4];
            }
            #pragma unroll
            for (int ni = 0; ni < 4; ni++) {
                int rb = wn + ni * 8 + r;
                bf[ni][0] = Bs[rb*36 + c]; bf[ni][1] = Bs[rb*36 + c + 4];
            }
            #pragma unroll
            for (int mi = 0; mi < 4; mi++)
                #pragma unroll
                for (int ni = 0; ni < 4; ni++)
                    MMA8(acc[mi][ni], af[mi], bf[ni]);
        }
        __syncthreads();
    }
#undef GSTAGE
}

#define EPI_ROW(m0, wm, mi, rg) ((m0) + (wm) + (mi)*16 + (lane >> 2) + (((rg) & 2) << 2))
#define EPI_COL(n0, wn, ni, rg) ((n0) + (wn) + (ni)*8 + ((lane & 3) << 1) + ((rg) & 1))

// ============================================================
// QKV projection -> q/k/v [B,H,T,D] (tf32 bits; K d-permuted)
// ============================================================
__global__ __launch_bounds__(256) void k_qkv(const float* __restrict__ bias) {
    extern __shared__ unsigned dsm[];
    float acc[4][4][4] = {};
    const int m0 = blockIdx.y * 128, n0 = blockIdx.x * 128;
    gemm_nt_cp<E_>(g_ci, E_, g_cwin, E_, m0, n0, acc, dsm);
    const int lane = threadIdx.x & 31, warp = threadIdx.x >> 5;
    const int wm = (warp >> 2) * 64, wn = (warp & 3) * 32;
    #pragma unroll
    for (int mi = 0; mi < 4; mi++)
        #pragma unroll
        for (int ni = 0; ni < 4; ni++)
            #pragma unroll
            for (int rg = 0; rg < 4; rg++) {
                int row = EPI_ROW(m0, wm, mi, rg);
                int col = EPI_COL(n0, wn, ni, rg);
                float v = __uint_as_float(f2tf32(acc[mi][ni][rg] + bias[col]));
                int t = row / B_, b = row % B_;
                int sec = col >> 9, h = (col >> 6) & 7, d = col & 63;
                if (sec == 1)   // K: permute d so (k, k+4) pairs are adjacent
                    d = (d & 56) | (((d & 3) << 1) | ((d >> 2) & 1));
                float* dst = (sec == 0) ? g_q : (sec == 1) ? g_k : g_v;
                dst[(((size_t)(b * H_ + h) * T_) + t) * D_ + d] = v;
            }
}

// ============================================================
// pos projection -> g_r[H,R,D] (tf32 bits)
// ============================================================
__global__ __launch_bounds__(256) void k_pos(const float* __restrict__ bias) {
    extern __shared__ unsigned dsm[];
    float acc[4][4][4] = {};
    const int m0 = blockIdx.y * 128, n0 = blockIdx.x * 128;
    gemm_nt_cp<E_>(g_cpos, E_, g_cwpos, E_, m0, n0, acc, dsm);
    const int lane = threadIdx.x & 31, warp = threadIdx.x >> 5;
    const int wm = (warp >> 2) * 64, wn = (warp & 3) * 32;
    #pragma unroll
    for (int mi = 0; mi < 4; mi++)
        #pragma unroll
        for (int ni = 0; ni < 4; ni++)
            #pragma unroll
            for (int rg = 0; rg < 4; rg++) {
                int rr = EPI_ROW(m0, wm, mi, rg);
                int col = EPI_COL(n0, wn, ni, rg);
                int h = col >> 6, d = col & 63;
                g_r[((size_t)h * T_ + rr) * D_ + d] =
                    __uint_as_float(f2tf32(acc[mi][ni][rg] + bias[col]));
            }
}

// ============================================================
// br[h][c] = rrb_h · r[h,c]   (bias term of BD, folded out of MMA)
// ============================================================
__global__ __launch_bounds__(128) void k_brdot(const float* __restrict__ rrb) {
    int idx = blockIdx.x * 128 + threadIdx.x;   // h*T + c
    int h = idx >> 11;
    const float4* rr = (const float4*)(g_r + (size_t)idx * D_);
    const float4* bb = (const float4*)(rrb + h * D_);
    float s = 0.f;
    #pragma unroll
    for (int i = 0; i < 16; i++) {
        float4 a = rr[i], b = bb[i];
        s += a.x*b.x + a.y*b.y + a.z*b.z + a.w*b.w;
    }
    g_br[idx] = s;
}

// ============================================================
// BD: raw[t,c] = q[t]·r[c] + br[c], written PRE-SHIFTED + scaled fp16.
// Shift bijection: c >= T-1-t -> (t, c+t-(T-1)); else t>=1 -> (t-1, c+t+1).
// Coalesced: tile staged fp16 in smem, rows written contiguously.
// ============================================================
__global__ __launch_bounds__(256) void k_bd() {
    extern __shared__ unsigned dsm[];
    const int bh = blockIdx.z, h = bh & 7;
    float acc[4][4][4] = {};
    const int m0 = blockIdx.y * 128, n0 = blockIdx.x * 128;
    gemm_nt_cp<D_>(g_q + (size_t)bh * T_ * D_, D_,
                   g_r + (size_t)h  * T_ * D_, D_, m0, n0, acc, dsm);

    const int tid = threadIdx.x, lane = tid & 31, warp = tid >> 5;
    const int wm = (warp >> 2) * 64, wn = (warp & 3) * 32;
    __half* Hs = (__half*)dsm;                 // [128][136] halfs
    const float* br = g_br + h * T_;
    #pragma unroll
    for (int mi = 0; mi < 4; mi++)
        #pragma unroll
        for (int ni = 0; ni < 4; ni++)
            #pragma unroll
            for (int rg = 0; rg < 4; rg++) {
                int lt = wm + mi*16 + (lane >> 2) + (((rg) & 2) << 2);
                int lc = wn + ni*8 + ((lane & 3) << 1) + ((rg) & 1);
                float v = (acc[mi][ni][rg] + br[n0 + lc]) * SCL;
                Hs[lt * 136 + lc] = __float2half_rn(v);
            }
    __syncthreads();

    __half* out = g_BDs + (size_t)bh * T_ * T_;
    for (int i = 0; i < 16; i++) {
        int lt = warp * 16 + i;
        int t = m0 + lt;
        int cut = (T_ - 1) - t - n0;           // local c < cut -> wrap segment
        cut = min(max(cut, 0), 128);
        #pragma unroll
        for (int j = 0; j < 4; j++) {
            int cl = lane * 4 + j;
            __half v = Hs[lt * 136 + cl];
            int c = n0 + cl;
            if (cl >= cut)
                out[(size_t)t * T_ + (c + t - (T_ - 1))] = v;
            else if (t >= 1)
                out[(size_t)(t - 1) * T_ + (c + t + 1)] = v;
        }
    }
}

// ============================================================
// Flash attention (pipelined; K d-paired -> LDS.64 B-fragments)
// ============================================================
__global__ __launch_bounds__(256, 1) void k_flash(const float* __restrict__ rwb) {
    extern __shared__ unsigned smem[];
    const int BUFW = 128*72 + 128*72;      // K + V words per buffer
    unsigned* Ps = smem + 2 * BUFW;        // [128][132] words

    const int bh = blockIdx.y, h = bh & 7, b = bh >> 3;
    const int t0 = blockIdx.x * 128;
    const float*  Q  = g_q + (size_t)bh * T_ * D_;
    const float*  K  = g_k + (size_t)bh * T_ * D_;
    const float*  V  = g_v + (size_t)bh * T_ * D_;
    const __half* BD = g_BDs + (size_t)bh * T_ * T_;

    const int tid = threadIdx.x, lane = tid & 31, warp = tid >> 5;
    const int r = lane >> 2, cc = lane & 3;
    const int row0 = warp * 16;
    const int trow0 = t0 + row0 + r, trow1 = trow0 + 8;

#define PREFETCH_KV(buf, s0_) do {                                            \
    unsigned* Kb_ = smem + (buf) * BUFW;                                      \
    unsigned* Vb_ = Kb_ + 128*72;                                             \
    _Pragma("unroll")                                                         \
    for (int i_ = 0; i_ < 8; i_++) {                                          \
        int idx_ = tid + i_ * 256;                                            \
        int row_ = idx_ >> 4, c4_ = (idx_ & 15) * 4;                          \
        cpa16(Kb_ + row_*72 + c4_, K + (size_t)((s0_) + row_) * D_ + c4_);    \
        cpa16(Vb_ + row_*72 + c4_, V + (size_t)((s0_) + row_) * D_ + c4_);    \
    }                                                                         \
    asm volatile("cp.async.commit_group;" ::: "memory");                      \
} while (0)

#define PREFETCH_BD(s0_) do {                                                 \
    _Pragma("unroll")                                                         \
    for (int i_ = 0; i_ < 8; i_++) {                                          \
        int idx_ = lane + i_ * 32;                                            \
        int row_ = idx_ >> 4, c16_ = idx_ & 15;                               \
        cpa16(Ps + (row0 + row_) * 132 + c16_ * 4,                            \
              BD + (size_t)(t0 + row0 + row_) * T_ + (s0_) + c16_ * 8);       \
    }                                                                         \
    asm volatile("cp.async.commit_group;" ::: "memory");                      \
} while (0)

    // q fragments, prescaled
    unsigned aq[8][4];
    const float* rwbh = rwb + h * D_;
    #pragma unroll
    for (int kc = 0; kc < 8; kc++) {
        int c0 = kc * 8 + cc;
        aq[kc][0] = f2tf32((Q[(size_t)trow0 * D_ + c0]     + rwbh[c0])     * SCL);
        aq[kc][1] = f2tf32((Q[(size_t)trow1 * D_ + c0]     + rwbh[c0])     * SCL);
        aq[kc][2] = f2tf32((Q[(size_t)trow0 * D_ + c0 + 4] + rwbh[c0 + 4]) * SCL);
        aq[kc][3] = f2tf32((Q[(size_t)trow1 * D_ + c0 + 4] + rwbh[c0 + 4]) * SCL);
    }

    PREFETCH_KV(0, 0);
    PREFETCH_BD(0);

    float oacc[8][4] = {};
    float m0r = -1e30f, m1r = -1e30f, l0 = 0.f, l1 = 0.f;

    #pragma unroll 1
    for (int it = 0; it < T_ / 128; it++) {
        const int s0 = it * 128;
        const int cur = it & 1;
        asm volatile("cp.async.wait_group 1;" ::: "memory");   // KV(it)
        __syncthreads();

        PREFETCH_KV(cur ^ 1, (s0 + 128) & (T_ - 1));

        const unsigned* Kb = smem + cur * BUFW;
        const unsigned* Vb = Kb + 128*72;

        // ---- AC = qw · K^T (K d-paired -> LDS.64) ----
        float pacc[16][4];
        #pragma unroll
        for (int nt = 0; nt < 16; nt++)
            #pragma unroll
            for (int j = 0; j < 4; j++) pacc[nt][j] = 0.f;
        #pragma unroll
        for (int kc = 0; kc < 8; kc++) {
            #pragma unroll
            for (int nt = 0; nt < 16; nt++) {
                int srow = nt * 8 + r;
                uint2 kb2 = *(const uint2*)(Kb + srow * 72 + kc * 8 + 2 * cc);
                unsigned bf[2] = { kb2.x, kb2.y };
                MMA8(pacc[nt], aq[kc], bf);
            }
        }

        asm volatile("cp.async.wait_group 1;" ::: "memory");   // BD(it)
        __syncwarp();

        // ---- add BD (mask s==t+1), row max ----
        const __half2* bd0 = (const __half2*)(Ps + (row0 + r) * 132);
        const __half2* bd1 = (const __half2*)(Ps + (row0 + r + 8) * 132);
        float pm0 = -1e30f, pm1 = -1e30f;
        #pragma unroll
        for (int nt = 0; nt < 16; nt++) {
            int sb = s0 + nt * 8 + 2 * cc;
            float2 f0 = __half22float2(bd0[4 * nt + cc]);
            float2 f1 = __half22float2(bd1[4 * nt + cc]);
            pacc[nt][0] += (sb     == trow0 + 1) ? 0.f : f0.x;
            pacc[nt][1] += (sb + 1 == trow0 + 1) ? 0.f : f0.y;
            pacc[nt][2] += (sb     == trow1 + 1) ? 0.f : f1.x;
            pacc[nt][3] += (sb + 1 == trow1 + 1) ? 0.f : f1.y;
            pm0 = fmaxf(pm0, fmaxf(pacc[nt][0], pacc[nt][1]));
            pm1 = fmaxf(pm1, fmaxf(pacc[nt][2], pacc[nt][3]));
        }
        pm0 = fmaxf(pm0, __shfl_xor_sync(0xffffffffu, pm0, 1));
        pm0 = fmaxf(pm0, __shfl_xor_sync(0xffffffffu, pm0, 2));
        pm1 = fmaxf(pm1, __shfl_xor_sync(0xffffffffu, pm1, 1));
        pm1 = fmaxf(pm1, __shfl_xor_sync(0xffffffffu, pm1, 2));

        float mn0 = fmaxf(m0r, pm0), mn1 = fmaxf(m1r, pm1);
        float sf0 = ex2f(m0r - mn0), sf1 = ex2f(m1r - mn1);
        m0r = mn0; m1r = mn1;
        #pragma unroll
        for (int nt = 0; nt < 8; nt++) {
            oacc[nt][0] *= sf0; oacc[nt][1] *= sf0;
            oacc[nt][2] *= sf1; oacc[nt][3] *= sf1;
        }
        l0 *= sf0; l1 *= sf1;

        // ---- exp, rowsum, store P over BD in Ps ----
        float sum0 = 0.f, sum1 = 0.f;
        #pragma unroll
        for (int nt = 0; nt < 16; nt++) {
            float e0 = ex2f(pacc[nt][0] - mn0);
            float e1 = ex2f(pacc[nt][1] - mn0);
            float e2 = ex2f(pacc[nt][2] - mn1);
            float e3 = ex2f(pacc[nt][3] - mn1);
            sum0 += e0 + e1; sum1 += e2 + e3;
            int col = nt * 8 + 2 * cc;
            uint2 p0 = { f2tf32(e0), f2tf32(e1) };
            *(uint2*)(Ps + (row0 + r) * 132 + col) = p0;
            uint2 p1 = { f2tf32(e2), f2tf32(e3) };
            *(uint2*)(Ps + (row0 + r + 8) * 132 + col) = p1;
        }
        sum0 += __shfl_xor_sync(0xffffffffu, sum0, 1);
        sum0 += __shfl_xor_sync(0xffffffffu, sum0, 2);
        sum1 += __shfl_xor_sync(0xffffffffu, sum1, 1);
        sum1 += __shfl_xor_sync(0xffffffffu, sum1, 2);
        l0 += sum0; l1 += sum1;

        __syncwarp();

        // ---- O += P · V ----
        #pragma unroll
        for (int kc = 0; kc < 16; kc++) {
            unsigned af[4];
            af[0] = Ps[(row0 + r) * 132 + kc * 8 + cc];
            af[1] = Ps[(row0 + r + 8) * 132 + kc * 8 + cc];
            af[2] = Ps[(row0 + r) * 132 + kc * 8 + cc + 4];
            af[3] = Ps[(row0 + r + 8) * 132 + kc * 8 + cc + 4];
            #pragma unroll
            for (int nt = 0; nt < 8; nt++) {
                unsigned bf[2];
                bf[0] = Vb[(kc * 8 + cc) * 72 + nt * 8 + r];
                bf[1] = Vb[(kc * 8 + cc + 4) * 72 + nt * 8 + r];
                MMA8(oacc[nt], af, bf);
            }
        }
        __syncwarp();

        if (it < T_ / 128 - 1)
            PREFETCH_BD(s0 + 128);
    }
    asm volatile("cp.async.wait_group 0;" ::: "memory");

    // ---- epilogue: O /= l -> g_ctx (tf32 bits) ----
    float il0 = 1.f / l0, il1 = 1.f / l1;
    #pragma unroll
    for (int nt = 0; nt < 8; nt++) {
        int d = h * 64 + nt * 8 + 2 * cc;
        uint2 o0 = { f2tf32(oacc[nt][0] * il0), f2tf32(oacc[nt][1] * il0) };
        *(uint2*)(g_ctx + ((size_t)trow0 * B_ + b) * E_ + d) = o0;
        uint2 o1 = { f2tf32(oacc[nt][2] * il1), f2tf32(oacc[nt][3] * il1) };
        *(uint2*)(g_ctx + ((size_t)trow1 * B_ + b) * E_ + d) = o1;
    }
#undef PREFETCH_KV
#undef PREFETCH_BD
}

// ============================================================
// out projection (final output stays fp32)
// ============================================================
__global__ __launch_bounds__(256) void k_out(const float* __restrict__ bias,
                                             float* __restrict__ out) {
    extern __shared__ unsigned dsm[];
    float acc[4][4][4] = {};
    const int m0 = blockIdx.y * 128, n0 = blockIdx.x * 128;
    gemm_nt_cp<E_>(g_ctx, E_, g_cwout, E_, m0, n0, acc, dsm);
    const int lane = threadIdx.x & 31, warp = threadIdx.x >> 5;
    const int wm = (warp >> 2) * 64, wn = (warp & 3) * 32;
    #pragma unroll
    for (int mi = 0; mi < 4; mi++)
        #pragma unroll
        for (int ni = 0; ni < 4; ni++)
            #pragma unroll
            for (int rg = 0; rg < 4; rg++) {
                int row = EPI_ROW(m0, wm, mi, rg);
                int col = EPI_COL(n0, wn, ni, rg);
                out[(size_t)row * E_ + col] = acc[mi][ni][rg] + bias[col];
            }
}

// ============================================================
extern "C" void kernel_launch(void* const* d_in, const int* in_sizes, int n_in,
                              void* d_out, int out_size) {
    const float* input = (const float*)d_in[0];
    const float* pos   = (const float*)d_in[1];
    const float* w_in  = (const float*)d_in[2];
    const float* w_out = (const float*)d_in[3];
    const float* w_pos = (const float*)d_in[4];
    const float* b_in  = (const float*)d_in[5];
    const float* b_out = (const float*)d_in[6];
    const float* b_pos = (const float*)d_in[7];
    const float* rwb   = (const float*)d_in[8];
    const float* rrb   = (const float*)d_in[9];
    float* out = (float*)d_out;

    const int gemm_smem  = 2 * 2 * 128 * 36 * 4;                     // 73728
    const int flash_smem = (2 * (128*72 + 128*72) + 128*132) * 4;    // 215040
    cudaFuncSetAttribute(k_qkv,  cudaFuncAttributeMaxDynamicSharedMemorySize, gemm_smem);
    cudaFuncSetAttribute(k_pos,  cudaFuncAttributeMaxDynamicSharedMemorySize, gemm_smem);
    cudaFuncSetAttribute(k_bd,   cudaFuncAttributeMaxDynamicSharedMemorySize, gemm_smem);
    cudaFuncSetAttribute(k_out,  cudaFuncAttributeMaxDynamicSharedMemorySize, gemm_smem);
    cudaFuncSetAttribute(k_flash, cudaFuncAttributeMaxDynamicSharedMemorySize, flash_smem);

    // pointer fetch for __device__ scratch copies
    float *p_ci, *p_cpos, *p_cwin, *p_cwout, *p_cwpos;
    cudaGetSymbolAddress((void**)&p_ci,    g_ci);
    cudaGetSymbolAddress((void**)&p_cpos,  g_cpos);
    cudaGetSymbolAddress((void**)&p_cwin,  g_cwin);
    cudaGetSymbolAddress((void**)&p_cwout, g_cwout);
    cudaGetSymbolAddress((void**)&p_cwpos, g_cwpos);

    k_cvt<<<(T_*B_*E_/4 + 255)/256, 256>>>(p_ci,    input, T_*B_*E_/4);
    k_cvt<<<(T_*E_/4    + 255)/256, 256>>>(p_cpos,  pos,   T_*E_/4);
    k_cvt<<<(E3_*E_/4   + 255)/256, 256>>>(p_cwin,  w_in,  E3_*E_/4);
    k_cvt<<<(E_*E_/4    + 255)/256, 256>>>(p_cwout, w_out, E_*E_/4);
    k_cvt<<<(E_*E_/4    + 255)/256, 256>>>(p_cwpos, w_pos, E_*E_/4);

    k_qkv  <<<dim3(E3_/128, (T_*B_)/128), 256, gemm_smem>>>(b_in);
    k_pos  <<<dim3(E_/128,  T_/128),      256, gemm_smem>>>(b_pos);
    k_brdot<<<H_*T_/128, 128>>>(rrb);
    k_bd   <<<dim3(T_/128, T_/128, B_*H_), 256, gemm_smem>>>();
    k_flash<<<dim3(T_/128, B_*H_), 256, flash_smem>>>(rwb);
    k_out  <<<dim3(E_/128, (T_*B_)/128), 256, gemm_smem>>>(b_out, out);
}

// round 6
// speedup vs baseline: 4.4042x; 1.0842x over previous
#include <cuda_runtime.h>
#include <cuda_fp16.h>
#include <math.h>

#define T_  2048
#define B_  2
#define E_  512
#define H_  8
#define D_  64
#define E3_ 1536

// scale * log2(e): softmax in base-2 domain
#define SCL 0.1803368801111204f

// ---- scratch (__device__ globals: allocation-guard-legal) ----
__device__ float g_q[B_*H_*T_*D_];            // [B,H,T,D] tf32-bits
__device__ float g_k[B_*H_*T_*D_];            // [B,H,T,D] tf32-bits, d-permuted
__device__ float g_v[B_*H_*T_*D_];            // [B,H,T,D] tf32-bits
__device__ float g_r[H_*T_*D_];               // [H,R,D]   tf32-bits
__device__ float g_br[H_*T_];                 // rrb_h · r[h,c]
__device__ __half g_BDs[(size_t)B_*H_*T_*T_]; // BD, PRE-SHIFTED + scaled, fp16
__device__ float g_ctx[T_*B_*E_];             // [T,B,E]   tf32-bits
// tf32-rounded copies of harness inputs (enables raw cp.async GEMMs)
__device__ float g_ci[T_*B_*E_];
__device__ float g_cpos[T_*E_];
__device__ float g_cwin[E3_*E_];
__device__ float g_cwout[E_*E_];
__device__ float g_cwpos[E_*E_];

__device__ __forceinline__ unsigned f2tf32(float x) {
    unsigned r;
    asm("cvt.rna.tf32.f32 %0, %1;" : "=r"(r) : "f"(x));
    return r;
}
__device__ __forceinline__ float ex2f(float x) {
    float y;
    asm("ex2.approx.ftz.f32 %0, %1;" : "=f"(y) : "f"(x));
    return y;
}
__device__ __forceinline__ void cpa16(void* d, const void* s) {
    unsigned a = (unsigned)__cvta_generic_to_shared(d);
    asm volatile("cp.async.cg.shared.global [%0], [%1], 16;" :: "r"(a), "l"(s));
}

#define MMA8(d, a, b) \
  asm volatile("mma.sync.aligned.m16n8k8.row.col.f32.tf32.tf32.f32 " \
      "{%0,%1,%2,%3},{%4,%5,%6,%7},{%8,%9},{%0,%1,%2,%3};" \
      : "+f"((d)[0]), "+f"((d)[1]), "+f"((d)[2]), "+f"((d)[3]) \
      : "r"((a)[0]), "r"((a)[1]), "r"((a)[2]), "r"((a)[3]), \
        "r"((b)[0]), "r"((b)[1]))

// ============================================================
// One-shot tf32-rounding of all fp32 inputs (merged, vec4)
// ============================================================
#define N4_CI   (T_*B_*E_/4)
#define N4_CPOS (T_*E_/4)
#define N4_CWIN (E3_*E_/4)
#define N4_CW   (E_*E_/4)
#define N4_TOT  (N4_CI + N4_CPOS + N4_CWIN + 2*N4_CW)

__global__ __launch_bounds__(256) void k_cvt_all(const float* __restrict__ s0,
                                                 const float* __restrict__ s1,
                                                 const float* __restrict__ s2,
                                                 const float* __restrict__ s3,
                                                 const float* __restrict__ s4) {
    int i = blockIdx.x * 256 + threadIdx.x;
    if (i >= N4_TOT) return;
    const float* src; float* dst; int off = i;
    if (i < N4_CI)                               { src = s0; dst = g_ci; }
    else if ((off -= N4_CI)   < N4_CPOS)         { src = s1; dst = g_cpos; }
    else if ((off -= N4_CPOS) < N4_CWIN)         { src = s2; dst = g_cwin; }
    else if ((off -= N4_CWIN) < N4_CW)           { src = s3; dst = g_cwout; }
    else { off -= N4_CW;                           src = s4; dst = g_cwpos; }
    float4 v = ((const float4*)src)[off];
    uint4 u = { f2tf32(v.x), f2tf32(v.y), f2tf32(v.z), f2tf32(v.w) };
    ((uint4*)dst)[off] = u;
}

// ============================================================
// Double-buffered cp.async NT mainloop: C[128,128] = A·Bt^T.
// Operands pre-rounded tf32 bits (raw bytes -> MMA).
// ============================================================
template<int KTOT>
__device__ __forceinline__ void gemm_nt_cp(const float* __restrict__ A, int lda,
                                           const float* __restrict__ Bt, int ldb,
                                           int m0, int n0, float acc[4][4][4],
                                           unsigned* sm) {
    const int tid = threadIdx.x;
    const int lane = tid & 31, warp = tid >> 5;
    const int wm = (warp >> 2) * 64, wn = (warp & 3) * 32;

#define GSTAGE(buf_, k0_) do {                                                \
    unsigned* As_ = sm + (buf_) * 9216;                                       \
    unsigned* Bs_ = As_ + 4608;                                               \
    _Pragma("unroll")                                                         \
    for (int i_ = 0; i_ < 4; i_++) {                                          \
        int idx_ = tid + i_ * 256;                                            \
        int row_ = idx_ >> 3, c4_ = (idx_ & 7) * 4;                           \
        cpa16(As_ + row_*36 + c4_, A  + (size_t)(m0 + row_) * lda + (k0_) + c4_); \
        cpa16(Bs_ + row_*36 + c4_, Bt + (size_t)(n0 + row_) * ldb + (k0_) + c4_); \
    }                                                                         \
    asm volatile("cp.async.commit_group;" ::: "memory");                      \
} while (0)

    GSTAGE(0, 0);
    #pragma unroll 1
    for (int k0 = 0; k0 < KTOT; k0 += 32) {
        const int buf = (k0 >> 5) & 1;
        const bool more = (k0 + 32 < KTOT);
        if (more) GSTAGE(buf ^ 1, k0 + 32);
        if (more) asm volatile("cp.async.wait_group 1;" ::: "memory");
        else      asm volatile("cp.async.wait_group 0;" ::: "memory");
        __syncthreads();

        const unsigned* As = sm + buf * 9216;
        const unsigned* Bs = As + 4608;
        #pragma unroll
        for (int ks = 0; ks < 4; ks++) {
            const int kk = ks * 8;
            const int r = lane >> 2, c = kk + (lane & 3);
            unsigned af[4][4], bf[4][2];
            #pragma unroll
            for (int mi = 0; mi < 4; mi++) {
                int rr = wm + mi * 16 + r;
                af[mi][0] = As[rr*36 + c];     af[mi][1] = As[(rr+8)*36 + c];
                af[mi][2] = As[rr*36 + c + 4]; af[mi][3] = As[(rr+8)*36 + c + 4];
            }
            #pragma unroll
            for (int ni = 0; ni < 4; ni++) {
                int rb = wn + ni * 8 + r;
                bf[ni][0] = Bs[rb*36 + c]; bf[ni][1] = Bs[rb*36 + c + 4];
            }
            #pragma unroll
            for (int mi = 0; mi < 4; mi++)
                #pragma unroll
                for (int ni = 0; ni < 4; ni++)
                    MMA8(acc[mi][ni], af[mi], bf[ni]);
        }
        __syncthreads();
    }
#undef GSTAGE
}

#define EPI_ROW(m0, wm, mi, rg) ((m0) + (wm) + (mi)*16 + (lane >> 2) + (((rg) & 2) << 2))
#define EPI_COL(n0, wn, ni, rg) ((n0) + (wn) + (ni)*8 + ((lane & 3) << 1) + ((rg) & 1))

// ============================================================
// QKV projection -> q/k/v [B,H,T,D] (tf32 bits; K d-permuted)
// ============================================================
__global__ __launch_bounds__(256) void k_qkv(const float* __restrict__ bias) {
    extern __shared__ unsigned dsm[];
    float acc[4][4][4] = {};
    const int m0 = blockIdx.y * 128, n0 = blockIdx.x * 128;
    gemm_nt_cp<E_>(g_ci, E_, g_cwin, E_, m0, n0, acc, dsm);
    const int lane = threadIdx.x & 31, warp = threadIdx.x >> 5;
    const int wm = (warp >> 2) * 64, wn = (warp & 3) * 32;
    #pragma unroll
    for (int mi = 0; mi < 4; mi++)
        #pragma unroll
        for (int ni = 0; ni < 4; ni++)
            #pragma unroll
            for (int rg = 0; rg < 4; rg++) {
                int row = EPI_ROW(m0, wm, mi, rg);
                int col = EPI_COL(n0, wn, ni, rg);
                float v = __uint_as_float(f2tf32(acc[mi][ni][rg] + bias[col]));
                int t = row / B_, b = row % B_;
                int sec = col >> 9, h = (col >> 6) & 7, d = col & 63;
                if (sec == 1)   // K: permute d so (k, k+4) pairs are adjacent
                    d = (d & 56) | (((d & 3) << 1) | ((d >> 2) & 1));
                float* dst = (sec == 0) ? g_q : (sec == 1) ? g_k : g_v;
                dst[(((size_t)(b * H_ + h) * T_) + t) * D_ + d] = v;
            }
}

// ============================================================
// pos projection -> g_r[H,R,D] (tf32 bits)
// ============================================================
__global__ __launch_bounds__(256) void k_pos(const float* __restrict__ bias) {
    extern __shared__ unsigned dsm[];
    float acc[4][4][4] = {};
    const int m0 = blockIdx.y * 128, n0 = blockIdx.x * 128;
    gemm_nt_cp<E_>(g_cpos, E_, g_cwpos, E_, m0, n0, acc, dsm);
    const int lane = threadIdx.x & 31, warp = threadIdx.x >> 5;
    const int wm = (warp >> 2) * 64, wn = (warp & 3) * 32;
    #pragma unroll
    for (int mi = 0; mi < 4; mi++)
        #pragma unroll
        for (int ni = 0; ni < 4; ni++)
            #pragma unroll
            for (int rg = 0; rg < 4; rg++) {
                int rr = EPI_ROW(m0, wm, mi, rg);
                int col = EPI_COL(n0, wn, ni, rg);
                int h = col >> 6, d = col & 63;
                g_r[((size_t)h * T_ + rr) * D_ + d] =
                    __uint_as_float(f2tf32(acc[mi][ni][rg] + bias[col]));
            }
}

// ============================================================
// br[h][c] = rrb_h · r[h,c]
// ============================================================
__global__ __launch_bounds__(128) void k_brdot(const float* __restrict__ rrb) {
    int idx = blockIdx.x * 128 + threadIdx.x;   // h*T + c
    int h = idx >> 11;
    const float4* rr = (const float4*)(g_r + (size_t)idx * D_);
    const float4* bb = (const float4*)(rrb + h * D_);
    float s = 0.f;
    #pragma unroll
    for (int i = 0; i < 16; i++) {
        float4 a = rr[i], b = bb[i];
        s += a.x*b.x + a.y*b.y + a.z*b.z + a.w*b.w;
    }
    g_br[idx] = s;
}

// ============================================================
// BD: raw[t,c] = q[t]·r[c] + br[c], written PRE-SHIFTED + scaled fp16.
// Shift bijection: c >= T-1-t -> (t, c+t-(T-1)); else t>=1 -> (t-1, c+t+1).
// Epilogue: smem-staged rows, parity-aligned __half2 segment copies
// (128B contiguous payload per warp store -> full sector efficiency).
// ============================================================
__global__ __launch_bounds__(256) void k_bd() {
    extern __shared__ unsigned dsm[];
    const int bh = blockIdx.z, h = bh & 7;
    float acc[4][4][4] = {};
    const int m0 = blockIdx.y * 128, n0 = blockIdx.x * 128;
    gemm_nt_cp<D_>(g_q + (size_t)bh * T_ * D_, D_,
                   g_r + (size_t)h  * T_ * D_, D_, m0, n0, acc, dsm);

    const int tid = threadIdx.x, lane = tid & 31, warp = tid >> 5;
    const int wm = (warp >> 2) * 64, wn = (warp & 3) * 32;
    __half* Hs = (__half*)dsm;                 // [128][136] halfs
    const float* br = g_br + h * T_;
    #pragma unroll
    for (int mi = 0; mi < 4; mi++)
        #pragma unroll
        for (int ni = 0; ni < 4; ni++)
            #pragma unroll
            for (int rg = 0; rg < 4; rg++) {
                int lt = wm + mi*16 + (lane >> 2) + (((rg) & 2) << 2);
                int lc = wn + ni*8 + ((lane & 3) << 1) + ((rg) & 1);
                float v = (acc[mi][ni][rg] + br[n0 + lc]) * SCL;
                Hs[lt * 136 + lc] = __float2half_rn(v);
            }
    __syncthreads();

    __half* out = g_BDs + (size_t)bh * T_ * T_;
    for (int i = 0; i < 16; i++) {
        int lt = warp * 16 + i;
        int t = m0 + lt;
        int cut = (T_ - 1) - t - n0;
        cut = min(max(cut, 0), 128);
        const __half* src = Hs + lt * 136;

        // segment A: cl in [cut,128) -> row t, cols start n0+cut+t-(T-1)
        {
            int len = 128 - cut;
            if (len > 0) {
                size_t dst = (size_t)t * T_ + (n0 + cut + t - (T_ - 1));
                int so = cut;
                int k0 = (int)(dst & 1);
                if (k0 && lane == 0) out[dst] = src[so];
                for (int k = k0 + 2 * lane; k + 1 < len; k += 64) {
                    __half2 v = { src[so + k], src[so + k + 1] };
                    *(__half2*)(out + dst + k) = v;
                }
                if (((len - k0) & 1) && lane == 0) out[dst + len - 1] = src[so + len - 1];
            }
        }
        // segment B: cl in [0,cut) -> row t-1, cols start n0+t+1
        if (t >= 1 && cut > 0) {
            int len = cut;
            size_t dst = (size_t)(t - 1) * T_ + (n0 + t + 1);
            int k0 = (int)(dst & 1);
            if (k0 && lane == 0) out[dst] = src[0];
            for (int k = k0 + 2 * lane; k + 1 < len; k += 64) {
                __half2 v = { src[k], src[k + 1] };
                *(__half2*)(out + dst + k) = v;
            }
            if (((len - k0) & 1) && lane == 0) out[dst + len - 1] = src[len - 1];
        }
    }
}

// ============================================================
// Flash attention: t-tile 128, s-tile 64, 2 CTAs/SM.
// K/V + BD cp.async pipelined as before, halved per-stage footprint.
// ============================================================
__global__ __launch_bounds__(256, 2) void k_flash(const float* __restrict__ rwb) {
    extern __shared__ unsigned smem[];
    const int BUFW = 64*72 * 2;            // K + V words per stage (64 rows each)
    unsigned* Ps = smem + 2 * BUFW;        // [128][68] words; BD in words 0..31/row

    const int bh = blockIdx.y, h = bh & 7, b = bh >> 3;
    const int t0 = blockIdx.x * 128;
    const float*  Q  = g_q + (size_t)bh * T_ * D_;
    const float*  K  = g_k + (size_t)bh * T_ * D_;
    const float*  V  = g_v + (size_t)bh * T_ * D_;
    const __half* BD = g_BDs + (size_t)bh * T_ * T_;

    const int tid = threadIdx.x, lane = tid & 31, warp = tid >> 5;
    const int r = lane >> 2, cc = lane & 3;
    const int row0 = warp * 16;
    const int trow0 = t0 + row0 + r, trow1 = trow0 + 8;

#define PREFETCH_KV(buf, s0_) do {                                            \
    unsigned* Kb_ = smem + (buf) * BUFW;                                      \
    unsigned* Vb_ = Kb_ + 64*72;                                              \
    _Pragma("unroll")                                                         \
    for (int i_ = 0; i_ < 4; i_++) {                                          \
        int idx_ = tid + i_ * 256;                                            \
        int row_ = idx_ >> 4, c4_ = (idx_ & 15) * 4;                          \
        cpa16(Kb_ + row_*72 + c4_, K + (size_t)((s0_) + row_) * D_ + c4_);    \
        cpa16(Vb_ + row_*72 + c4_, V + (size_t)((s0_) + row_) * D_ + c4_);    \
    }                                                                         \
    asm volatile("cp.async.commit_group;" ::: "memory");                      \
} while (0)

#define PREFETCH_BD(s0_) do {                                                 \
    _Pragma("unroll")                                                         \
    for (int i_ = 0; i_ < 4; i_++) {                                          \
        int idx_ = lane + i_ * 32;                                            \
        int row_ = idx_ >> 3, c16_ = idx_ & 7;                                \
        cpa16(Ps + (row0 + row_) * 68 + c16_ * 4,                             \
              BD + (size_t)(t0 + row0 + row_) * T_ + (s0_) + c16_ * 8);       \
    }                                                                         \
    asm volatile("cp.async.commit_group;" ::: "memory");                      \
} while (0)

    // q fragments, prescaled
    unsigned aq[8][4];
    const float* rwbh = rwb + h * D_;
    #pragma unroll
    for (int kc = 0; kc < 8; kc++) {
        int c0 = kc * 8 + cc;
        aq[kc][0] = f2tf32((Q[(size_t)trow0 * D_ + c0]     + rwbh[c0])     * SCL);
        aq[kc][1] = f2tf32((Q[(size_t)trow1 * D_ + c0]     + rwbh[c0])     * SCL);
        aq[kc][2] = f2tf32((Q[(size_t)trow0 * D_ + c0 + 4] + rwbh[c0 + 4]) * SCL);
        aq[kc][3] = f2tf32((Q[(size_t)trow1 * D_ + c0 + 4] + rwbh[c0 + 4]) * SCL);
    }

    PREFETCH_KV(0, 0);
    PREFETCH_BD(0);

    float oacc[8][4] = {};
    float m0r = -1e30f, m1r = -1e30f, l0 = 0.f, l1 = 0.f;

    #pragma unroll 1
    for (int it = 0; it < T_ / 64; it++) {
        const int s0 = it * 64;
        const int cur = it & 1;
        asm volatile("cp.async.wait_group 1;" ::: "memory");   // KV(it)
        __syncthreads();

        PREFETCH_KV(cur ^ 1, (s0 + 64) & (T_ - 1));

        const unsigned* Kb = smem + cur * BUFW;
        const unsigned* Vb = Kb + 64*72;

        // ---- AC = qw · K^T (K d-paired -> LDS.64) ----
        float pacc[8][4];
        #pragma unroll
        for (int nt = 0; nt < 8; nt++)
            #pragma unroll
            for (int j = 0; j < 4; j++) pacc[nt][j] = 0.f;
        #pragma unroll
        for (int kc = 0; kc < 8; kc++) {
            #pragma unroll
            for (int nt = 0; nt < 8; nt++) {
                int srow = nt * 8 + r;
                uint2 kb2 = *(const uint2*)(Kb + srow * 72 + kc * 8 + 2 * cc);
                unsigned bf[2] = { kb2.x, kb2.y };
                MMA8(pacc[nt], aq[kc], bf);
            }
        }

        asm volatile("cp.async.wait_group 1;" ::: "memory");   // BD(it)
        __syncwarp();

        // ---- add BD (mask s==t+1), row max ----
        const __half2* bd0 = (const __half2*)(Ps + (row0 + r) * 68);
        const __half2* bd1 = (const __half2*)(Ps + (row0 + r + 8) * 68);
        float pm0 = -1e30f, pm1 = -1e30f;
        #pragma unroll
        for (int nt = 0; nt < 8; nt++) {
            int sb = s0 + nt * 8 + 2 * cc;
            float2 f0 = __half22float2(bd0[4 * nt + cc]);
            float2 f1 = __half22float2(bd1[4 * nt + cc]);
            pacc[nt][0] += (sb     == trow0 + 1) ? 0.f : f0.x;
            pacc[nt][1] += (sb + 1 == trow0 + 1) ? 0.f : f0.y;
            pacc[nt][2] += (sb     == trow1 + 1) ? 0.f : f1.x;
            pacc[nt][3] += (sb + 1 == trow1 + 1) ? 0.f : f1.y;
            pm0 = fmaxf(pm0, fmaxf(pacc[nt][0], pacc[nt][1]));
            pm1 = fmaxf(pm1, fmaxf(pacc[nt][2], pacc[nt][3]));
        }
        pm0 = fmaxf(pm0, __shfl_xor_sync(0xffffffffu, pm0, 1));
        pm0 = fmaxf(pm0, __shfl_xor_sync(0xffffffffu, pm0, 2));
        pm1 = fmaxf(pm1, __shfl_xor_sync(0xffffffffu, pm1, 1));
        pm1 = fmaxf(pm1, __shfl_xor_sync(0xffffffffu, pm1, 2));

        float mn0 = fmaxf(m0r, pm0), mn1 = fmaxf(m1r, pm1);
        float sf0 = ex2f(m0r - mn0), sf1 = ex2f(m1r - mn1);
        m0r = mn0; m1r = mn1;
        #pragma unroll
        for (int nt = 0; nt < 8; nt++) {
            oacc[nt][0] *= sf0; oacc[nt][1] *= sf0;
            oacc[nt][2] *= sf1; oacc[nt][3] *= sf1;
        }
        l0 *= sf0; l1 *= sf1;

        // ---- exp, rowsum, store P over BD in Ps ----
        float sum0 = 0.f, sum1 = 0.f;
        #pragma unroll
        for (int nt = 0; nt < 8; nt++) {
            float e0 = ex2f(pacc[nt][0] - mn0);
            float e1 = ex2f(pacc[nt][1] - mn0);
            float e2 = ex2f(pacc[nt][2] - mn1);
            float e3 = ex2f(pacc[nt][3] - mn1);
            sum0 += e0 + e1; sum1 += e2 + e3;
            int col = nt * 8 + 2 * cc;
            uint2 p0 = { f2tf32(e0), f2tf32(e1) };
            *(uint2*)(Ps + (row0 + r) * 68 + col) = p0;
            uint2 p1 = { f2tf32(e2), f2tf32(e3) };
            *(uint2*)(Ps + (row0 + r + 8) * 68 + col) = p1;
        }
        sum0 += __shfl_xor_sync(0xffffffffu, sum0, 1);
        sum0 += __shfl_xor_sync(0xffffffffu, sum0, 2);
        sum1 += __shfl_xor_sync(0xffffffffu, sum1, 1);
        sum1 += __shfl_xor_sync(0xffffffffu, sum1, 2);
        l0 += sum0; l1 += sum1;

        __syncwarp();

        // ---- O += P · V ----
        #pragma unroll
        for (int kc = 0; kc < 8; kc++) {
            unsigned af[4];
            af[0] = Ps[(row0 + r) * 68 + kc * 8 + cc];
            af[1] = Ps[(row0 + r + 8) * 68 + kc * 8 + cc];
            af[2] = Ps[(row0 + r) * 68 + kc * 8 + cc + 4];
            af[3] = Ps[(row0 + r + 8) * 68 + kc * 8 + cc + 4];
            #pragma unroll
            for (int nt = 0; nt < 8; nt++) {
                unsigned bf[2];
                bf[0] = Vb[(kc * 8 + cc) * 72 + nt * 8 + r];
                bf[1] = Vb[(kc * 8 + cc + 4) * 72 + nt * 8 + r];
                MMA8(oacc[nt], af, bf);
            }
        }
        __syncwarp();

        if (it < T_ / 64 - 1)
            PREFETCH_BD(s0 + 64);
    }
    asm volatile("cp.async.wait_group 0;" ::: "memory");

    // ---- epilogue: O /= l -> g_ctx (tf32 bits) ----
    float il0 = 1.f / l0, il1 = 1.f / l1;
    #pragma unroll
    for (int nt = 0; nt < 8; nt++) {
        int d = h * 64 + nt * 8 + 2 * cc;
        uint2 o0 = { f2tf32(oacc[nt][0] * il0), f2tf32(oacc[nt][1] * il0) };
        *(uint2*)(g_ctx + ((size_t)trow0 * B_ + b) * E_ + d) = o0;
        uint2 o1 = { f2tf32(oacc[nt][2] * il1), f2tf32(oacc[nt][3] * il1) };
        *(uint2*)(g_ctx + ((size_t)trow1 * B_ + b) * E_ + d) = o1;
    }
#undef PREFETCH_KV
#undef PREFETCH_BD
}

// ============================================================
// out projection (final output stays fp32)
// ============================================================
__global__ __launch_bounds__(256) void k_out(const float* __restrict__ bias,
                                             float* __restrict__ out) {
    extern __shared__ unsigned dsm[];
    float acc[4][4][4] = {};
    const int m0 = blockIdx.y * 128, n0 = blockIdx.x * 128;
    gemm_nt_cp<E_>(g_ctx, E_, g_cwout, E_, m0, n0, acc, dsm);
    const int lane = threadIdx.x & 31, warp = threadIdx.x >> 5;
    const int wm = (warp >> 2) * 64, wn = (warp & 3) * 32;
    #pragma unroll
    for (int mi = 0; mi < 4; mi++)
        #pragma unroll
        for (int ni = 0; ni < 4; ni++)
            #pragma unroll
            for (int rg = 0; rg < 4; rg++) {
                int row = EPI_ROW(m0, wm, mi, rg);
                int col = EPI_COL(n0, wn, ni, rg);
                out[(size_t)row * E_ + col] = acc[mi][ni][rg] + bias[col];
            }
}

// ============================================================
extern "C" void kernel_launch(void* const* d_in, const int* in_sizes, int n_in,
                              void* d_out, int out_size) {
    const float* input = (const float*)d_in[0];
    const float* pos   = (const float*)d_in[1];
    const float* w_in  = (const float*)d_in[2];
    const float* w_out = (const float*)d_in[3];
    const float* w_pos = (const float*)d_in[4];
    const float* b_in  = (const float*)d_in[5];
    const float* b_out = (const float*)d_in[6];
    const float* b_pos = (const float*)d_in[7];
    const float* rwb   = (const float*)d_in[8];
    const float* rrb   = (const float*)d_in[9];
    float* out = (float*)d_out;

    const int gemm_smem  = 2 * 2 * 128 * 36 * 4;                     // 73728
    const int flash_smem = (2 * (64*72*2) + 128*68) * 4;             // 108544
    cudaFuncSetAttribute(k_qkv,  cudaFuncAttributeMaxDynamicSharedMemorySize, gemm_smem);
    cudaFuncSetAttribute(k_pos,  cudaFuncAttributeMaxDynamicSharedMemorySize, gemm_smem);
    cudaFuncSetAttribute(k_bd,   cudaFuncAttributeMaxDynamicSharedMemorySize, gemm_smem);
    cudaFuncSetAttribute(k_out,  cudaFuncAttributeMaxDynamicSharedMemorySize, gemm_smem);
    cudaFuncSetAttribute(k_flash, cudaFuncAttributeMaxDynamicSharedMemorySize, flash_smem);

    k_cvt_all<<<(N4_TOT + 255)/256, 256>>>(input, pos, w_in, w_out, w_pos);

    k_qkv  <<<dim3(E3_/128, (T_*B_)/128), 256, gemm_smem>>>(b_in);
    k_pos  <<<dim3(E_/128,  T_/128),      256, gemm_smem>>>(b_pos);
    k_brdot<<<H_*T_/128, 128>>>(rrb);
    k_bd   <<<dim3(T_/128, T_/128, B_*H_), 256, gemm_smem>>>();
    k_flash<<<dim3(T_/128, B_*H_), 256, flash_smem>>>(rwb);
    k_out  <<<dim3(E_/128, (T_*B_)/128), 256, gemm_smem>>>(b_out, out);
}

// round 7
// speedup vs baseline: 5.3625x; 1.2176x over previous
#include <cuda_runtime.h>
#include <cuda_fp16.h>
#include <math.h>

#define T_  2048
#define B_  2
#define E_  512
#define H_  8
#define D_  64
#define E3_ 1536

// scale * log2(e): softmax in base-2 domain
#define SCL 0.1803368801111204f

// ---- scratch (__device__ globals: allocation-guard-legal) ----
__device__ __half g_q[B_*H_*T_*D_];           // [B,H,T,D] fp16
__device__ __half g_k[B_*H_*T_*D_];           // [B,H,T,D] fp16, d uint-pair-permuted
__device__ float  g_v[B_*H_*T_*D_];           // [B,H,T,D] tf32-bits (PV stays tf32)
__device__ __half g_r[H_*T_*D_];              // [H,R,D]   fp16
__device__ float  g_br[H_*T_];                // rrb_h · r[h,c]
__device__ __half g_BDs[(size_t)B_*H_*T_*T_]; // BD, PRE-SHIFTED + scaled, fp16
__device__ __half g_ctx[T_*B_*E_];            // [T,B,E]   fp16
// fp16 copies of harness inputs (raw cp.async GEMM operands)
__device__ __half g_ci[T_*B_*E_];
__device__ __half g_cpos[T_*E_];
__device__ __half g_cwin[E3_*E_];
__device__ __half g_cwout[E_*E_];
__device__ __half g_cwpos[E_*E_];

__device__ __forceinline__ unsigned f2tf32(float x) {
    unsigned r;
    asm("cvt.rna.tf32.f32 %0, %1;" : "=r"(r) : "f"(x));
    return r;
}
__device__ __forceinline__ float ex2f(float x) {
    float y;
    asm("ex2.approx.ftz.f32 %0, %1;" : "=f"(y) : "f"(x));
    return y;
}
__device__ __forceinline__ void cpa16(void* d, const void* s) {
    unsigned a = (unsigned)__cvta_generic_to_shared(d);
    asm volatile("cp.async.cg.shared.global [%0], [%1], 16;" :: "r"(a), "l"(s));
}

// tf32 mma (PV path)
#define MMA8(d, a, b) \
  asm volatile("mma.sync.aligned.m16n8k8.row.col.f32.tf32.tf32.f32 " \
      "{%0,%1,%2,%3},{%4,%5,%6,%7},{%8,%9},{%0,%1,%2,%3};" \
      : "+f"((d)[0]), "+f"((d)[1]), "+f"((d)[2]), "+f"((d)[3]) \
      : "r"((a)[0]), "r"((a)[1]), "r"((a)[2]), "r"((a)[3]), \
        "r"((b)[0]), "r"((b)[1]))

// fp16 mma, fp32 accum
#define MMA16(d, a, b) \
  asm volatile("mma.sync.aligned.m16n8k16.row.col.f32.f16.f16.f32 " \
      "{%0,%1,%2,%3},{%4,%5,%6,%7},{%8,%9},{%0,%1,%2,%3};" \
      : "+f"((d)[0]), "+f"((d)[1]), "+f"((d)[2]), "+f"((d)[3]) \
      : "r"((a)[0]), "r"((a)[1]), "r"((a)[2]), "r"((a)[3]), \
        "r"((b)[0]), "r"((b)[1]))

// ============================================================
// One-shot fp32 -> fp16 conversion of all inputs (merged)
// ============================================================
#define N4_CI   (T_*B_*E_/4)
#define N4_CPOS (T_*E_/4)
#define N4_CWIN (E3_*E_/4)
#define N4_CW   (E_*E_/4)
#define N4_TOT  (N4_CI + N4_CPOS + N4_CWIN + 2*N4_CW)

__global__ __launch_bounds__(256) void k_cvt_all(const float* __restrict__ s0,
                                                 const float* __restrict__ s1,
                                                 const float* __restrict__ s2,
                                                 const float* __restrict__ s3,
                                                 const float* __restrict__ s4) {
    int i = blockIdx.x * 256 + threadIdx.x;
    if (i >= N4_TOT) return;
    const float* src; __half* dst; int off = i;
    if (i < N4_CI)                               { src = s0; dst = g_ci; }
    else if ((off -= N4_CI)   < N4_CPOS)         { src = s1; dst = g_cpos; }
    else if ((off -= N4_CPOS) < N4_CWIN)         { src = s2; dst = g_cwin; }
    else if ((off -= N4_CWIN) < N4_CW)           { src = s3; dst = g_cwout; }
    else { off -= N4_CW;                           src = s4; dst = g_cwpos; }
    float4 v = ((const float4*)src)[off];
    __half2 h0 = __floats2half2_rn(v.x, v.y);
    __half2 h1 = __floats2half2_rn(v.z, v.w);
    uint2 u = { *(unsigned*)&h0, *(unsigned*)&h1 };
    ((uint2*)dst)[off] = u;
}

// ============================================================
// fp16 double-buffered cp.async NT mainloop: C[128,128] = A·Bt^T.
// smem chunk = 32 halfs (16 uints data, pitch 20) per row per stage.
// ============================================================
template<int KTOT>
__device__ __forceinline__ void gemm_nt_hp(const __half* __restrict__ A, int lda,
                                           const __half* __restrict__ Bt, int ldb,
                                           int m0, int n0, float acc[4][4][4],
                                           unsigned* sm) {
    const int tid = threadIdx.x;
    const int lane = tid & 31, warp = tid >> 5;
    const int wm = (warp >> 2) * 64, wn = (warp & 3) * 32;

#define HSTAGE(buf_, k0_) do {                                                \
    unsigned* As_ = sm + (buf_) * 5120;                                       \
    unsigned* Bs_ = As_ + 2560;                                               \
    _Pragma("unroll")                                                         \
    for (int i_ = 0; i_ < 2; i_++) {                                          \
        int idx_ = tid + i_ * 256;                                            \
        int row_ = idx_ >> 2, c8_ = (idx_ & 3) * 8;                           \
        cpa16(As_ + row_*20 + (idx_ & 3)*4, A  + (size_t)(m0 + row_) * lda + (k0_) + c8_); \
        cpa16(Bs_ + row_*20 + (idx_ & 3)*4, Bt + (size_t)(n0 + row_) * ldb + (k0_) + c8_); \
    }                                                                         \
    asm volatile("cp.async.commit_group;" ::: "memory");                      \
} while (0)

    HSTAGE(0, 0);
    #pragma unroll 1
    for (int k0 = 0; k0 < KTOT; k0 += 32) {
        const int buf = (k0 >> 5) & 1;
        const bool more = (k0 + 32 < KTOT);
        if (more) HSTAGE(buf ^ 1, k0 + 32);
        if (more) asm volatile("cp.async.wait_group 1;" ::: "memory");
        else      asm volatile("cp.async.wait_group 0;" ::: "memory");
        __syncthreads();

        const unsigned* As = sm + buf * 5120;
        const unsigned* Bs = As + 2560;
        #pragma unroll
        for (int ks = 0; ks < 2; ks++) {
            const int r = lane >> 2, c = ks * 8 + (lane & 3);
            unsigned af[4][4], bf[4][2];
            #pragma unroll
            for (int mi = 0; mi < 4; mi++) {
                int rr = wm + mi * 16 + r;
                af[mi][0] = As[rr*20 + c];     af[mi][1] = As[(rr+8)*20 + c];
                af[mi][2] = As[rr*20 + c + 4]; af[mi][3] = As[(rr+8)*20 + c + 4];
            }
            #pragma unroll
            for (int ni = 0; ni < 4; ni++) {
                int rb = wn + ni * 8 + r;
                bf[ni][0] = Bs[rb*20 + c]; bf[ni][1] = Bs[rb*20 + c + 4];
            }
            #pragma unroll
            for (int mi = 0; mi < 4; mi++)
                #pragma unroll
                for (int ni = 0; ni < 4; ni++)
                    MMA16(acc[mi][ni], af[mi], bf[ni]);
        }
        __syncthreads();
    }
#undef HSTAGE
}

#define EPI_ROW(m0, wm, mi, rg) ((m0) + (wm) + (mi)*16 + (lane >> 2) + (((rg) & 2) << 2))
#define EPI_COL(n0, wn, ni, rg) ((n0) + (wn) + (ni)*8 + ((lane & 3) << 1) + ((rg) & 1))

// ============================================================
// QKV projection -> q/k fp16, v tf32 [B,H,T,D]; K uint-pair-permuted
// ============================================================
__global__ __launch_bounds__(256) void k_qkv(const float* __restrict__ bias) {
    extern __shared__ unsigned dsm[];
    float acc[4][4][4] = {};
    const int m0 = blockIdx.y * 128, n0 = blockIdx.x * 128;
    gemm_nt_hp<E_>(g_ci, E_, g_cwin, E_, m0, n0, acc, dsm);
    const int lane = threadIdx.x & 31, warp = threadIdx.x >> 5;
    const int wm = (warp >> 2) * 64, wn = (warp & 3) * 32;
    #pragma unroll
    for (int mi = 0; mi < 4; mi++)
        #pragma unroll
        for (int ni = 0; ni < 4; ni++)
            #pragma unroll
            for (int rg = 0; rg < 4; rg++) {
                int row = EPI_ROW(m0, wm, mi, rg);
                int col = EPI_COL(n0, wn, ni, rg);
                float v = acc[mi][ni][rg] + bias[col];
                int t = row / B_, b = row % B_;
                int sec = col >> 9, h = (col >> 6) & 7, d = col & 63;
                size_t base = (((size_t)(b * H_ + h) * T_) + t) * D_;
                if (sec == 0) {
                    g_q[base + d] = __float2half_rn(v);
                } else if (sec == 1) {
                    // permute so uint-pairs (u, u+4) within each k16 chunk are adjacent
                    int u = d >> 1;
                    int up = (u & 24) | ((u & 3) << 1) | ((u >> 2) & 1);
                    g_k[base + (up << 1 | (d & 1))] = __float2half_rn(v);
                } else {
                    g_v[base + d] = __uint_as_float(f2tf32(v));
                }
            }
}

// ============================================================
// pos projection -> g_r[H,R,D] fp16
// ============================================================
__global__ __launch_bounds__(256) void k_pos(const float* __restrict__ bias) {
    extern __shared__ unsigned dsm[];
    float acc[4][4][4] = {};
    const int m0 = blockIdx.y * 128, n0 = blockIdx.x * 128;
    gemm_nt_hp<E_>(g_cpos, E_, g_cwpos, E_, m0, n0, acc, dsm);
    const int lane = threadIdx.x & 31, warp = threadIdx.x >> 5;
    const int wm = (warp >> 2) * 64, wn = (warp & 3) * 32;
    #pragma unroll
    for (int mi = 0; mi < 4; mi++)
        #pragma unroll
        for (int ni = 0; ni < 4; ni++)
            #pragma unroll
            for (int rg = 0; rg < 4; rg++) {
                int rr = EPI_ROW(m0, wm, mi, rg);
                int col = EPI_COL(n0, wn, ni, rg);
                int h = col >> 6, d = col & 63;
                g_r[((size_t)h * T_ + rr) * D_ + d] =
                    __float2half_rn(acc[mi][ni][rg] + bias[col]);
            }
}

// ============================================================
// br[h][c] = rrb_h · r[h,c]
// ============================================================
__global__ __launch_bounds__(128) void k_brdot(const float* __restrict__ rrb) {
    int idx = blockIdx.x * 128 + threadIdx.x;   // h*T + c
    int h = idx >> 11;
    const __half2* rr = (const __half2*)(g_r + (size_t)idx * D_);
    const float* bb = rrb + h * D_;
    float s = 0.f;
    #pragma unroll
    for (int i = 0; i < 32; i++) {
        float2 a = __half22float2(rr[i]);
        s += a.x * bb[2*i] + a.y * bb[2*i + 1];
    }
    g_br[idx] = s;
}

// ============================================================
// BD: raw[t,c] = q[t]·r[c] + br[c], written PRE-SHIFTED + scaled fp16.
// ============================================================
__global__ __launch_bounds__(256) void k_bd() {
    extern __shared__ unsigned dsm[];
    const int bh = blockIdx.z, h = bh & 7;
    float acc[4][4][4] = {};
    const int m0 = blockIdx.y * 128, n0 = blockIdx.x * 128;
    gemm_nt_hp<D_>(g_q + (size_t)bh * T_ * D_, D_,
                   g_r + (size_t)h  * T_ * D_, D_, m0, n0, acc, dsm);

    const int tid = threadIdx.x, lane = tid & 31, warp = tid >> 5;
    const int wm = (warp >> 2) * 64, wn = (warp & 3) * 32;
    __half* Hs = (__half*)dsm;                 // [128][136] halfs
    const float* br = g_br + h * T_;
    #pragma unroll
    for (int mi = 0; mi < 4; mi++)
        #pragma unroll
        for (int ni = 0; ni < 4; ni++)
            #pragma unroll
            for (int rg = 0; rg < 4; rg++) {
                int lt = wm + mi*16 + (lane >> 2) + (((rg) & 2) << 2);
                int lc = wn + ni*8 + ((lane & 3) << 1) + ((rg) & 1);
                float v = (acc[mi][ni][rg] + br[n0 + lc]) * SCL;
                Hs[lt * 136 + lc] = __float2half_rn(v);
            }
    __syncthreads();

    __half* out = g_BDs + (size_t)bh * T_ * T_;
    for (int i = 0; i < 16; i++) {
        int lt = warp * 16 + i;
        int t = m0 + lt;
        int cut = (T_ - 1) - t - n0;
        cut = min(max(cut, 0), 128);
        const __half* src = Hs + lt * 136;

        // segment A: cl in [cut,128) -> row t
        {
            int len = 128 - cut;
            if (len > 0) {
                size_t dst = (size_t)t * T_ + (n0 + cut + t - (T_ - 1));
                int so = cut;
                int k0 = (int)(dst & 1);
                if (k0 && lane == 0) out[dst] = src[so];
                for (int k = k0 + 2 * lane; k + 1 < len; k += 64) {
                    __half2 v = { src[so + k], src[so + k + 1] };
                    *(__half2*)(out + dst + k) = v;
                }
                if (((len - k0) & 1) && lane == 0) out[dst + len - 1] = src[so + len - 1];
            }
        }
        // segment B: cl in [0,cut) -> row t-1
        if (t >= 1 && cut > 0) {
            int len = cut;
            size_t dst = (size_t)(t - 1) * T_ + (n0 + t + 1);
            int k0 = (int)(dst & 1);
            if (k0 && lane == 0) out[dst] = src[0];
            for (int k = k0 + 2 * lane; k + 1 < len; k += 64) {
                __half2 v = { src[k], src[k + 1] };
                *(__half2*)(out + dst + k) = v;
            }
            if (((len - k0) & 1) && lane == 0) out[dst + len - 1] = src[len - 1];
        }
    }
}

// ============================================================
// Flash attention: t-tile 128, s-tile 64, 2 CTAs/SM.
// AC in fp16 (K fp16, d-permuted, pitch 40 -> uint2 LDS.64).
// PV in tf32 (V tf32, P tf32) — unchanged path.
// ============================================================
__global__ __launch_bounds__(256, 2) void k_flash(const float* __restrict__ rwb) {
    extern __shared__ unsigned smem[];
    const int KW = 64 * 40;                 // K tile words (fp16, pitch 40 uints)
    const int VW = 64 * 72;                 // V tile words (tf32)
    const int BUFW = KW + VW;               // 7168 words per stage
    unsigned* Ps = smem + 2 * BUFW;         // [128][68] words

    const int bh = blockIdx.y, h = bh & 7, b = bh >> 3;
    const int t0 = blockIdx.x * 128;
    const __half* Q  = g_q + (size_t)bh * T_ * D_;
    const __half* K  = g_k + (size_t)bh * T_ * D_;
    const float*  V  = g_v + (size_t)bh * T_ * D_;
    const __half* BD = g_BDs + (size_t)bh * T_ * T_;

    const int tid = threadIdx.x, lane = tid & 31, warp = tid >> 5;
    const int r = lane >> 2, cc = lane & 3;
    const int row0 = warp * 16;
    const int trow0 = t0 + row0 + r, trow1 = trow0 + 8;

#define PREFETCH_KV(buf, s0_) do {                                            \
    unsigned* Kb_ = smem + (buf) * BUFW;                                      \
    unsigned* Vb_ = Kb_ + KW;                                                 \
    _Pragma("unroll")                                                         \
    for (int i_ = 0; i_ < 2; i_++) {      /* K: 64 rows x 8 chunks */         \
        int idx_ = tid + i_ * 256;                                            \
        int row_ = idx_ >> 3, ch_ = idx_ & 7;                                 \
        cpa16(Kb_ + row_*40 + ch_*4, K + (size_t)((s0_) + row_) * D_ + ch_*8);\
    }                                                                         \
    _Pragma("unroll")                                                         \
    for (int i_ = 0; i_ < 4; i_++) {      /* V: 64 rows x 16 chunks */        \
        int idx_ = tid + i_ * 256;                                            \
        int row_ = idx_ >> 4, c4_ = (idx_ & 15) * 4;                          \
        cpa16(Vb_ + row_*72 + c4_, V + (size_t)((s0_) + row_) * D_ + c4_);    \
    }                                                                         \
    asm volatile("cp.async.commit_group;" ::: "memory");                      \
} while (0)

#define PREFETCH_BD(s0_) do {                                                 \
    _Pragma("unroll")                                                         \
    for (int i_ = 0; i_ < 4; i_++) {                                          \
        int idx_ = lane + i_ * 32;                                            \
        int row_ = idx_ >> 3, c16_ = idx_ & 7;                                \
        cpa16(Ps + (row0 + row_) * 68 + c16_ * 4,                             \
              BD + (size_t)(t0 + row0 + row_) * T_ + (s0_) + c16_ * 8);       \
    }                                                                         \
    asm volatile("cp.async.commit_group;" ::: "memory");                      \
} while (0)

    // q fragments (fp16 m16n8k16 A layout), prescaled + rwb
    unsigned aq[4][4];
    const float* rwbh = rwb + h * D_;
    #pragma unroll
    for (int kc = 0; kc < 4; kc++) {
        int c0 = kc * 16 + 2 * cc;
        #pragma unroll
        for (int half8 = 0; half8 < 2; half8++) {
            int c = c0 + half8 * 8;
            float2 q0 = __half22float2(*(const __half2*)(Q + (size_t)trow0 * D_ + c));
            float2 q1 = __half22float2(*(const __half2*)(Q + (size_t)trow1 * D_ + c));
            __half2 a0 = __floats2half2_rn((q0.x + rwbh[c]) * SCL, (q0.y + rwbh[c+1]) * SCL);
            __half2 a1 = __floats2half2_rn((q1.x + rwbh[c]) * SCL, (q1.y + rwbh[c+1]) * SCL);
            aq[kc][half8 * 2]     = *(unsigned*)&a0;   // a0 / a2
            aq[kc][half8 * 2 + 1] = *(unsigned*)&a1;   // a1 / a3
        }
    }

    PREFETCH_KV(0, 0);
    PREFETCH_BD(0);

    float oacc[8][4] = {};
    float m0r = -1e30f, m1r = -1e30f, l0 = 0.f, l1 = 0.f;

    #pragma unroll 1
    for (int it = 0; it < T_ / 64; it++) {
        const int s0 = it * 64;
        const int cur = it & 1;
        asm volatile("cp.async.wait_group 1;" ::: "memory");   // KV(it)
        __syncthreads();

        PREFETCH_KV(cur ^ 1, (s0 + 64) & (T_ - 1));

        const unsigned* Kb = smem + cur * BUFW;
        const unsigned* Vb = Kb + KW;

        // ---- AC = qw · K^T (fp16; uint2 B-frag via permute) ----
        float pacc[8][4];
        #pragma unroll
        for (int nt = 0; nt < 8; nt++)
            #pragma unroll
            for (int j = 0; j < 4; j++) pacc[nt][j] = 0.f;
        #pragma unroll
        for (int kc = 0; kc < 4; kc++) {
            #pragma unroll
            for (int nt = 0; nt < 8; nt++) {
                int srow = nt * 8 + r;
                uint2 kb2 = *(const uint2*)(Kb + srow * 40 + kc * 8 + 2 * cc);
                unsigned bf[2] = { kb2.x, kb2.y };
                MMA16(pacc[nt], aq[kc], bf);
            }
        }

        asm volatile("cp.async.wait_group 1;" ::: "memory");   // BD(it)
        __syncwarp();

        // ---- add BD (mask s==t+1), row max ----
        const __half2* bd0 = (const __half2*)(Ps + (row0 + r) * 68);
        const __half2* bd1 = (const __half2*)(Ps + (row0 + r + 8) * 68);
        float pm0 = -1e30f, pm1 = -1e30f;
        #pragma unroll
        for (int nt = 0; nt < 8; nt++) {
            int sb = s0 + nt * 8 + 2 * cc;
            float2 f0 = __half22float2(bd0[4 * nt + cc]);
            float2 f1 = __half22float2(bd1[4 * nt + cc]);
            pacc[nt][0] += (sb     == trow0 + 1) ? 0.f : f0.x;
            pacc[nt][1] += (sb + 1 == trow0 + 1) ? 0.f : f0.y;
            pacc[nt][2] += (sb     == trow1 + 1) ? 0.f : f1.x;
            pacc[nt][3] += (sb + 1 == trow1 + 1) ? 0.f : f1.y;
            pm0 = fmaxf(pm0, fmaxf(pacc[nt][0], pacc[nt][1]));
            pm1 = fmaxf(pm1, fmaxf(pacc[nt][2], pacc[nt][3]));
        }
        pm0 = fmaxf(pm0, __shfl_xor_sync(0xffffffffu, pm0, 1));
        pm0 = fmaxf(pm0, __shfl_xor_sync(0xffffffffu, pm0, 2));
        pm1 = fmaxf(pm1, __shfl_xor_sync(0xffffffffu, pm1, 1));
        pm1 = fmaxf(pm1, __shfl_xor_sync(0xffffffffu, pm1, 2));

        float mn0 = fmaxf(m0r, pm0), mn1 = fmaxf(m1r, pm1);
        float sf0 = ex2f(m0r - mn0), sf1 = ex2f(m1r - mn1);
        m0r = mn0; m1r = mn1;
        #pragma unroll
        for (int nt = 0; nt < 8; nt++) {
            oacc[nt][0] *= sf0; oacc[nt][1] *= sf0;
            oacc[nt][2] *= sf1; oacc[nt][3] *= sf1;
        }
        l0 *= sf0; l1 *= sf1;

        // ---- exp, rowsum, store tf32 P over BD in Ps ----
        float sum0 = 0.f, sum1 = 0.f;
        #pragma unroll
        for (int nt = 0; nt < 8; nt++) {
            float e0 = ex2f(pacc[nt][0] - mn0);
            float e1 = ex2f(pacc[nt][1] - mn0);
            float e2 = ex2f(pacc[nt][2] - mn1);
            float e3 = ex2f(pacc[nt][3] - mn1);
            sum0 += e0 + e1; sum1 += e2 + e3;
            int col = nt * 8 + 2 * cc;
            uint2 p0 = { f2tf32(e0), f2tf32(e1) };
            *(uint2*)(Ps + (row0 + r) * 68 + col) = p0;
            uint2 p1 = { f2tf32(e2), f2tf32(e3) };
            *(uint2*)(Ps + (row0 + r + 8) * 68 + col) = p1;
        }
        sum0 += __shfl_xor_sync(0xffffffffu, sum0, 1);
        sum0 += __shfl_xor_sync(0xffffffffu, sum0, 2);
        sum1 += __shfl_xor_sync(0xffffffffu, sum1, 1);
        sum1 += __shfl_xor_sync(0xffffffffu, sum1, 2);
        l0 += sum0; l1 += sum1;

        __syncwarp();

        // ---- O += P · V (tf32) ----
        #pragma unroll
        for (int kc = 0; kc < 8; kc++) {
            unsigned af[4];
            af[0] = Ps[(row0 + r) * 68 + kc * 8 + cc];
            af[1] = Ps[(row0 + r + 8) * 68 + kc * 8 + cc];
            af[2] = Ps[(row0 + r) * 68 + kc * 8 + cc + 4];
            af[3] = Ps[(row0 + r + 8) * 68 + kc * 8 + cc + 4];
            #pragma unroll
            for (int nt = 0; nt < 8; nt++) {
                unsigned bf[2];
                bf[0] = Vb[(kc * 8 + cc) * 72 + nt * 8 + r];
                bf[1] = Vb[(kc * 8 + cc + 4) * 72 + nt * 8 + r];
                MMA8(oacc[nt], af, bf);
            }
        }
        __syncwarp();

        if (it < T_ / 64 - 1)
            PREFETCH_BD(s0 + 64);
    }
    asm volatile("cp.async.wait_group 0;" ::: "memory");

    // ---- epilogue: O /= l -> g_ctx (fp16) ----
    float il0 = 1.f / l0, il1 = 1.f / l1;
    #pragma unroll
    for (int nt = 0; nt < 8; nt++) {
        int d = h * 64 + nt * 8 + 2 * cc;
        __half2 o0 = __floats2half2_rn(oacc[nt][0] * il0, oacc[nt][1] * il0);
        *(__half2*)(g_ctx + ((size_t)trow0 * B_ + b) * E_ + d) = o0;
        __half2 o1 = __floats2half2_rn(oacc[nt][2] * il1, oacc[nt][3] * il1);
        *(__half2*)(g_ctx + ((size_t)trow1 * B_ + b) * E_ + d) = o1;
    }
#undef PREFETCH_KV
#undef PREFETCH_BD
}

// ============================================================
// out projection (fp16 GEMM, fp32 output)
// ============================================================
__global__ __launch_bounds__(256) void k_out(const float* __restrict__ bias,
                                             float* __restrict__ out) {
    extern __shared__ unsigned dsm[];
    float acc[4][4][4] = {};
    const int m0 = blockIdx.y * 128, n0 = blockIdx.x * 128;
    gemm_nt_hp<E_>(g_ctx, E_, g_cwout, E_, m0, n0, acc, dsm);
    const int lane = threadIdx.x & 31, warp = threadIdx.x >> 5;
    const int wm = (warp >> 2) * 64, wn = (warp & 3) * 32;
    #pragma unroll
    for (int mi = 0; mi < 4; mi++)
        #pragma unroll
        for (int ni = 0; ni < 4; ni++)
            #pragma unroll
            for (int rg = 0; rg < 4; rg++) {
                int row = EPI_ROW(m0, wm, mi, rg);
                int col = EPI_COL(n0, wn, ni, rg);
                out[(size_t)row * E_ + col] = acc[mi][ni][rg] + bias[col];
            }
}

// ============================================================
extern "C" void kernel_launch(void* const* d_in, const int* in_sizes, int n_in,
                              void* d_out, int out_size) {
    const float* input = (const float*)d_in[0];
    const float* pos   = (const float*)d_in[1];
    const float* w_in  = (const float*)d_in[2];
    const float* w_out = (const float*)d_in[3];
    const float* w_pos = (const float*)d_in[4];
    const float* b_in  = (const float*)d_in[5];
    const float* b_out = (const float*)d_in[6];
    const float* b_pos = (const float*)d_in[7];
    const float* rwb   = (const float*)d_in[8];
    const float* rrb   = (const float*)d_in[9];
    float* out = (float*)d_out;

    const int gemm_smem  = 2 * 2 * 128 * 20 * 4;                 // 40960
    const int bd_smem    = 128 * 136 * 2;                        // 34816 (epilogue halfs)
    const int kbd_smem   = gemm_smem > bd_smem ? gemm_smem : bd_smem;
    const int flash_smem = (2 * (64*40 + 64*72) + 128*68) * 4;   // 92160
    cudaFuncSetAttribute(k_qkv,  cudaFuncAttributeMaxDynamicSharedMemorySize, gemm_smem);
    cudaFuncSetAttribute(k_pos,  cudaFuncAttributeMaxDynamicSharedMemorySize, gemm_smem);
    cudaFuncSetAttribute(k_bd,   cudaFuncAttributeMaxDynamicSharedMemorySize, kbd_smem);
    cudaFuncSetAttribute(k_out,  cudaFuncAttributeMaxDynamicSharedMemorySize, gemm_smem);
    cudaFuncSetAttribute(k_flash, cudaFuncAttributeMaxDynamicSharedMemorySize, flash_smem);

    k_cvt_all<<<(N4_TOT + 255)/256, 256>>>(input, pos, w_in, w_out, w_pos);

    k_qkv  <<<dim3(E3_/128, (T_*B_)/128), 256, gemm_smem>>>(b_in);
    k_pos  <<<dim3(E_/128,  T_/128),      256, gemm_smem>>>(b_pos);
    k_brdot<<<H_*T_/128, 128>>>(rrb);
    k_bd   <<<dim3(T_/128, T_/128, B_*H_), 256, kbd_smem>>>();
    k_flash<<<dim3(T_/128, B_*H_), 256, flash_smem>>>(rwb);
    k_out  <<<dim3(E_/128, (T_*B_)/128), 256, gemm_smem>>>(b_out, out);
}

// round 8
// speedup vs baseline: 6.1650x; 1.1496x over previous
#include <cuda_runtime.h>
#include <cuda_fp16.h>
#include <math.h>

#define T_  2048
#define B_  2
#define E_  512
#define H_  8
#define D_  64
#define E3_ 1536

// scale * log2(e): softmax in base-2 domain
#define SCL 0.1803368801111204f

// ---- scratch (__device__ globals: allocation-guard-legal) ----
__device__ __half g_q[B_*H_*T_*D_];           // [B,H,T,D] fp16
__device__ __half g_k[B_*H_*T_*D_];           // [B,H,T,D] fp16, d uint-pair-permuted
__device__ __half g_v[B_*H_*D_*T_];           // [B,H,D,T] fp16 (TRANSPOSED for PV)
__device__ __half g_r[H_*T_*D_];              // [H,R,D]   fp16
__device__ float  g_br[H_*T_];                // rrb_h · r[h,c]
__device__ __half g_BDs[(size_t)B_*H_*T_*T_]; // BD, PRE-SHIFTED + scaled, fp16
__device__ __half g_ctx[T_*B_*E_];            // [T,B,E]   fp16
// fp16 copies of harness inputs (raw cp.async GEMM operands)
__device__ __half g_ci[T_*B_*E_];
__device__ __half g_cpos[T_*E_];
__device__ __half g_cwin[E3_*E_];
__device__ __half g_cwout[E_*E_];
__device__ __half g_cwpos[E_*E_];

__device__ __forceinline__ float ex2f(float x) {
    float y;
    asm("ex2.approx.ftz.f32 %0, %1;" : "=f"(y) : "f"(x));
    return y;
}
__device__ __forceinline__ void cpa16(void* d, const void* s) {
    unsigned a = (unsigned)__cvta_generic_to_shared(d);
    asm volatile("cp.async.cg.shared.global [%0], [%1], 16;" :: "r"(a), "l"(s));
}

// fp16 mma, fp32 accum
#define MMA16(d, a, b) \
  asm volatile("mma.sync.aligned.m16n8k16.row.col.f32.f16.f16.f32 " \
      "{%0,%1,%2,%3},{%4,%5,%6,%7},{%8,%9},{%0,%1,%2,%3};" \
      : "+f"((d)[0]), "+f"((d)[1]), "+f"((d)[2]), "+f"((d)[3]) \
      : "r"((a)[0]), "r"((a)[1]), "r"((a)[2]), "r"((a)[3]), \
        "r"((b)[0]), "r"((b)[1]))

// ============================================================
// One-shot fp32 -> fp16 conversion of all inputs (merged)
// ============================================================
#define N4_CI   (T_*B_*E_/4)
#define N4_CPOS (T_*E_/4)
#define N4_CWIN (E3_*E_/4)
#define N4_CW   (E_*E_/4)
#define N4_TOT  (N4_CI + N4_CPOS + N4_CWIN + 2*N4_CW)

__global__ __launch_bounds__(256) void k_cvt_all(const float* __restrict__ s0,
                                                 const float* __restrict__ s1,
                                                 const float* __restrict__ s2,
                                                 const float* __restrict__ s3,
                                                 const float* __restrict__ s4) {
    int i = blockIdx.x * 256 + threadIdx.x;
    if (i >= N4_TOT) return;
    const float* src; __half* dst; int off = i;
    if (i < N4_CI)                               { src = s0; dst = g_ci; }
    else if ((off -= N4_CI)   < N4_CPOS)         { src = s1; dst = g_cpos; }
    else if ((off -= N4_CPOS) < N4_CWIN)         { src = s2; dst = g_cwin; }
    else if ((off -= N4_CWIN) < N4_CW)           { src = s3; dst = g_cwout; }
    else { off -= N4_CW;                           src = s4; dst = g_cwpos; }
    float4 v = ((const float4*)src)[off];
    __half2 h0 = __floats2half2_rn(v.x, v.y);
    __half2 h1 = __floats2half2_rn(v.z, v.w);
    uint2 u = { *(unsigned*)&h0, *(unsigned*)&h1 };
    ((uint2*)dst)[off] = u;
}

// ============================================================
// fp16 double-buffered cp.async NT mainloop: C[128,128] = A·Bt^T.
// ============================================================
template<int KTOT>
__device__ __forceinline__ void gemm_nt_hp(const __half* __restrict__ A, int lda,
                                           const __half* __restrict__ Bt, int ldb,
                                           int m0, int n0, float acc[4][4][4],
                                           unsigned* sm) {
    const int tid = threadIdx.x;
    const int lane = tid & 31, warp = tid >> 5;
    const int wm = (warp >> 2) * 64, wn = (warp & 3) * 32;

#define HSTAGE(buf_, k0_) do {                                                \
    unsigned* As_ = sm + (buf_) * 5120;                                       \
    unsigned* Bs_ = As_ + 2560;                                               \
    _Pragma("unroll")                                                         \
    for (int i_ = 0; i_ < 2; i_++) {                                          \
        int idx_ = tid + i_ * 256;                                            \
        int row_ = idx_ >> 2, c8_ = (idx_ & 3) * 8;                           \
        cpa16(As_ + row_*20 + (idx_ & 3)*4, A  + (size_t)(m0 + row_) * lda + (k0_) + c8_); \
        cpa16(Bs_ + row_*20 + (idx_ & 3)*4, Bt + (size_t)(n0 + row_) * ldb + (k0_) + c8_); \
    }                                                                         \
    asm volatile("cp.async.commit_group;" ::: "memory");                      \
} while (0)

    HSTAGE(0, 0);
    #pragma unroll 1
    for (int k0 = 0; k0 < KTOT; k0 += 32) {
        const int buf = (k0 >> 5) & 1;
        const bool more = (k0 + 32 < KTOT);
        if (more) HSTAGE(buf ^ 1, k0 + 32);
        if (more) asm volatile("cp.async.wait_group 1;" ::: "memory");
        else      asm volatile("cp.async.wait_group 0;" ::: "memory");
        __syncthreads();

        const unsigned* As = sm + buf * 5120;
        const unsigned* Bs = As + 2560;
        #pragma unroll
        for (int ks = 0; ks < 2; ks++) {
            const int r = lane >> 2, c = ks * 8 + (lane & 3);
            unsigned af[4][4], bf[4][2];
            #pragma unroll
            for (int mi = 0; mi < 4; mi++) {
                int rr = wm + mi * 16 + r;
                af[mi][0] = As[rr*20 + c];     af[mi][1] = As[(rr+8)*20 + c];
                af[mi][2] = As[rr*20 + c + 4]; af[mi][3] = As[(rr+8)*20 + c + 4];
            }
            #pragma unroll
            for (int ni = 0; ni < 4; ni++) {
                int rb = wn + ni * 8 + r;
                bf[ni][0] = Bs[rb*20 + c]; bf[ni][1] = Bs[rb*20 + c + 4];
            }
            #pragma unroll
            for (int mi = 0; mi < 4; mi++)
                #pragma unroll
                for (int ni = 0; ni < 4; ni++)
                    MMA16(acc[mi][ni], af[mi], bf[ni]);
        }
        __syncthreads();
    }
#undef HSTAGE
}

#define EPI_ROW(m0, wm, mi, rg) ((m0) + (wm) + (mi)*16 + (lane >> 2) + (((rg) & 2) << 2))
#define EPI_COL(n0, wn, ni, rg) ((n0) + (wn) + (ni)*8 + ((lane & 3) << 1) + ((rg) & 1))

// ============================================================
// QKV projection -> q/k [B,H,T,D], v [B,H,D,T] (all fp16)
// ============================================================
__global__ __launch_bounds__(256) void k_qkv(const float* __restrict__ bias) {
    extern __shared__ unsigned dsm[];
    float acc[4][4][4] = {};
    const int m0 = blockIdx.y * 128, n0 = blockIdx.x * 128;
    gemm_nt_hp<E_>(g_ci, E_, g_cwin, E_, m0, n0, acc, dsm);
    const int lane = threadIdx.x & 31, warp = threadIdx.x >> 5;
    const int wm = (warp >> 2) * 64, wn = (warp & 3) * 32;
    #pragma unroll
    for (int mi = 0; mi < 4; mi++)
        #pragma unroll
        for (int ni = 0; ni < 4; ni++)
            #pragma unroll
            for (int rg = 0; rg < 4; rg++) {
                int row = EPI_ROW(m0, wm, mi, rg);
                int col = EPI_COL(n0, wn, ni, rg);
                float v = acc[mi][ni][rg] + bias[col];
                int t = row / B_, b = row % B_;
                int sec = col >> 9, h = (col >> 6) & 7, d = col & 63;
                if (sec == 0) {
                    g_q[(((size_t)(b * H_ + h) * T_) + t) * D_ + d] = __float2half_rn(v);
                } else if (sec == 1) {
                    // permute so uint-pairs (u, u+4) within each k16 chunk are adjacent
                    int u = d >> 1;
                    int up = (u & 24) | ((u & 3) << 1) | ((u >> 2) & 1);
                    g_k[(((size_t)(b * H_ + h) * T_) + t) * D_ + (up << 1 | (d & 1))] =
                        __float2half_rn(v);
                } else {
                    // V transposed: [B,H,D,T]
                    g_v[(((size_t)(b * H_ + h) * D_) + d) * T_ + t] = __float2half_rn(v);
                }
            }
}

// ============================================================
// pos projection -> g_r[H,R,D] fp16
// ============================================================
__global__ __launch_bounds__(256) void k_pos(const float* __restrict__ bias) {
    extern __shared__ unsigned dsm[];
    float acc[4][4][4] = {};
    const int m0 = blockIdx.y * 128, n0 = blockIdx.x * 128;
    gemm_nt_hp<E_>(g_cpos, E_, g_cwpos, E_, m0, n0, acc, dsm);
    const int lane = threadIdx.x & 31, warp = threadIdx.x >> 5;
    const int wm = (warp >> 2) * 64, wn = (warp & 3) * 32;
    #pragma unroll
    for (int mi = 0; mi < 4; mi++)
        #pragma unroll
        for (int ni = 0; ni < 4; ni++)
            #pragma unroll
            for (int rg = 0; rg < 4; rg++) {
                int rr = EPI_ROW(m0, wm, mi, rg);
                int col = EPI_COL(n0, wn, ni, rg);
                int h = col >> 6, d = col & 63;
                g_r[((size_t)h * T_ + rr) * D_ + d] =
                    __float2half_rn(acc[mi][ni][rg] + bias[col]);
            }
}

// ============================================================
// br[h][c] = rrb_h · r[h,c]
// ============================================================
__global__ __launch_bounds__(128) void k_brdot(const float* __restrict__ rrb) {
    int idx = blockIdx.x * 128 + threadIdx.x;   // h*T + c
    int h = idx >> 11;
    const __half2* rr = (const __half2*)(g_r + (size_t)idx * D_);
    const float* bb = rrb + h * D_;
    float s = 0.f;
    #pragma unroll
    for (int i = 0; i < 32; i++) {
        float2 a = __half22float2(rr[i]);
        s += a.x * bb[2*i] + a.y * bb[2*i + 1];
    }
    g_br[idx] = s;
}

// ============================================================
// BD: raw[t,c] = q[t]·r[c] + br[c], written PRE-SHIFTED + scaled fp16.
// ============================================================
__global__ __launch_bounds__(256) void k_bd() {
    extern __shared__ unsigned dsm[];
    const int bh = blockIdx.z, h = bh & 7;
    float acc[4][4][4] = {};
    const int m0 = blockIdx.y * 128, n0 = blockIdx.x * 128;
    gemm_nt_hp<D_>(g_q + (size_t)bh * T_ * D_, D_,
                   g_r + (size_t)h  * T_ * D_, D_, m0, n0, acc, dsm);

    const int tid = threadIdx.x, lane = tid & 31, warp = tid >> 5;
    const int wm = (warp >> 2) * 64, wn = (warp & 3) * 32;
    __half* Hs = (__half*)dsm;                 // [128][136] halfs
    const float* br = g_br + h * T_;
    #pragma unroll
    for (int mi = 0; mi < 4; mi++)
        #pragma unroll
        for (int ni = 0; ni < 4; ni++)
            #pragma unroll
            for (int rg = 0; rg < 4; rg++) {
                int lt = wm + mi*16 + (lane >> 2) + (((rg) & 2) << 2);
                int lc = wn + ni*8 + ((lane & 3) << 1) + ((rg) & 1);
                float v = (acc[mi][ni][rg] + br[n0 + lc]) * SCL;
                Hs[lt * 136 + lc] = __float2half_rn(v);
            }
    __syncthreads();

    __half* out = g_BDs + (size_t)bh * T_ * T_;
    for (int i = 0; i < 16; i++) {
        int lt = warp * 16 + i;
        int t = m0 + lt;
        int cut = (T_ - 1) - t - n0;
        cut = min(max(cut, 0), 128);
        const __half* src = Hs + lt * 136;

        // segment A: cl in [cut,128) -> row t
        {
            int len = 128 - cut;
            if (len > 0) {
                size_t dst = (size_t)t * T_ + (n0 + cut + t - (T_ - 1));
                int so = cut;
                int k0 = (int)(dst & 1);
                if (k0 && lane == 0) out[dst] = src[so];
                for (int k = k0 + 2 * lane; k + 1 < len; k += 64) {
                    __half2 v = { src[so + k], src[so + k + 1] };
                    *(__half2*)(out + dst + k) = v;
                }
                if (((len - k0) & 1) && lane == 0) out[dst + len - 1] = src[so + len - 1];
            }
        }
        // segment B: cl in [0,cut) -> row t-1
        if (t >= 1 && cut > 0) {
            int len = cut;
            size_t dst = (size_t)(t - 1) * T_ + (n0 + t + 1);
            int k0 = (int)(dst & 1);
            if (k0 && lane == 0) out[dst] = src[0];
            for (int k = k0 + 2 * lane; k + 1 < len; k += 64) {
                __half2 v = { src[k], src[k + 1] };
                *(__half2*)(out + dst + k) = v;
            }
            if (((len - k0) & 1) && lane == 0) out[dst + len - 1] = src[len - 1];
        }
    }
}

// ============================================================
// Flash attention: t-tile 128, s-tile 64, 2 CTAs/SM, all-fp16 MMA.
// P stays IN REGISTERS (AC C-frag == PV A-frag for m16n8k16).
// V transposed [d][s] in smem (pitch 36 words) -> half2 B-frags.
// ============================================================
__global__ __launch_bounds__(256, 2) void k_flash(const float* __restrict__ rwb) {
    extern __shared__ unsigned smem[];
    const int KW = 64 * 40;                 // K tile words (fp16, pitch 40)
    const int VW = 64 * 36;                 // V tile words (fp16 transposed, pitch 36)
    const int BUFW = KW + VW;               // 4864 words per stage
    unsigned* Ps = smem + 2 * BUFW;         // BD: [128][36] words (72-half pitch)

    const int bh = blockIdx.y, h = bh & 7, b = bh >> 3;
    const int t0 = blockIdx.x * 128;
    const __half* Q  = g_q + (size_t)bh * T_ * D_;
    const __half* K  = g_k + (size_t)bh * T_ * D_;
    const __half* V  = g_v + (size_t)bh * D_ * T_;   // [d][t]
    const __half* BD = g_BDs + (size_t)bh * T_ * T_;

    const int tid = threadIdx.x, lane = tid & 31, warp = tid >> 5;
    const int r = lane >> 2, cc = lane & 3;
    const int row0 = warp * 16;
    const int trow0 = t0 + row0 + r, trow1 = trow0 + 8;

#define PREFETCH_KV(buf, s0_) do {                                            \
    unsigned* Kb_ = smem + (buf) * BUFW;                                      \
    unsigned* Vb_ = Kb_ + KW;                                                 \
    _Pragma("unroll")                                                         \
    for (int i_ = 0; i_ < 2; i_++) {      /* K: 64 s-rows x 8 chunks */       \
        int idx_ = tid + i_ * 256;                                            \
        int row_ = idx_ >> 3, ch_ = idx_ & 7;                                 \
        cpa16(Kb_ + row_*40 + ch_*4, K + (size_t)((s0_) + row_) * D_ + ch_*8);\
    }                                                                         \
    _Pragma("unroll")                                                         \
    for (int i_ = 0; i_ < 2; i_++) {      /* V: 64 d-rows x 8 chunks */       \
        int idx_ = tid + i_ * 256;                                            \
        int row_ = idx_ >> 3, ch_ = idx_ & 7;                                 \
        cpa16(Vb_ + row_*36 + ch_*4, V + (size_t)row_ * T_ + (s0_) + ch_*8);  \
    }                                                                         \
    asm volatile("cp.async.commit_group;" ::: "memory");                      \
} while (0)

#define PREFETCH_BD(s0_) do {                                                 \
    _Pragma("unroll")                                                         \
    for (int i_ = 0; i_ < 4; i_++) {                                          \
        int idx_ = lane + i_ * 32;                                            \
        int row_ = idx_ >> 3, c16_ = idx_ & 7;                                \
        cpa16(Ps + (row0 + row_) * 36 + c16_ * 4,                             \
              BD + (size_t)(t0 + row0 + row_) * T_ + (s0_) + c16_ * 8);       \
    }                                                                         \
    asm volatile("cp.async.commit_group;" ::: "memory");                      \
} while (0)

    // q fragments (fp16 m16n8k16 A layout), prescaled + rwb
    unsigned aq[4][4];
    const float* rwbh = rwb + h * D_;
    #pragma unroll
    for (int kc = 0; kc < 4; kc++) {
        int c0 = kc * 16 + 2 * cc;
        #pragma unroll
        for (int half8 = 0; half8 < 2; half8++) {
            int c = c0 + half8 * 8;
            float2 q0 = __half22float2(*(const __half2*)(Q + (size_t)trow0 * D_ + c));
            float2 q1 = __half22float2(*(const __half2*)(Q + (size_t)trow1 * D_ + c));
            __half2 a0 = __floats2half2_rn((q0.x + rwbh[c]) * SCL, (q0.y + rwbh[c+1]) * SCL);
            __half2 a1 = __floats2half2_rn((q1.x + rwbh[c]) * SCL, (q1.y + rwbh[c+1]) * SCL);
            aq[kc][half8 * 2]     = *(unsigned*)&a0;
            aq[kc][half8 * 2 + 1] = *(unsigned*)&a1;
        }
    }

    PREFETCH_KV(0, 0);
    PREFETCH_BD(0);

    float oacc[8][4] = {};
    float m0r = -1e30f, m1r = -1e30f, l0 = 0.f, l1 = 0.f;

    #pragma unroll 1
    for (int it = 0; it < T_ / 64; it++) {
        const int s0 = it * 64;
        const int cur = it & 1;
        asm volatile("cp.async.wait_group 1;" ::: "memory");   // KV(it)
        __syncthreads();

        PREFETCH_KV(cur ^ 1, (s0 + 64) & (T_ - 1));

        const unsigned* Kb = smem + cur * BUFW;
        const unsigned* Vb = Kb + KW;

        // ---- AC = qw · K^T (fp16) ----
        float pacc[8][4];
        #pragma unroll
        for (int nt = 0; nt < 8; nt++)
            #pragma unroll
            for (int j = 0; j < 4; j++) pacc[nt][j] = 0.f;
        #pragma unroll
        for (int kc = 0; kc < 4; kc++) {
            #pragma unroll
            for (int nt = 0; nt < 8; nt++) {
                int srow = nt * 8 + r;
                uint2 kb2 = *(const uint2*)(Kb + srow * 40 + kc * 8 + 2 * cc);
                unsigned bf[2] = { kb2.x, kb2.y };
                MMA16(pacc[nt], aq[kc], bf);
            }
        }

        asm volatile("cp.async.wait_group 1;" ::: "memory");   // BD(it)
        __syncwarp();

        // ---- add BD (mask s==t+1), row max ----
        const __half2* bd0 = (const __half2*)(Ps + (row0 + r) * 36);
        const __half2* bd1 = (const __half2*)(Ps + (row0 + r + 8) * 36);
        float pm0 = -1e30f, pm1 = -1e30f;
        #pragma unroll
        for (int nt = 0; nt < 8; nt++) {
            int sb = s0 + nt * 8 + 2 * cc;
            float2 f0 = __half22float2(bd0[4 * nt + cc]);
            float2 f1 = __half22float2(bd1[4 * nt + cc]);
            pacc[nt][0] += (sb     == trow0 + 1) ? 0.f : f0.x;
            pacc[nt][1] += (sb + 1 == trow0 + 1) ? 0.f : f0.y;
            pacc[nt][2] += (sb     == trow1 + 1) ? 0.f : f1.x;
            pacc[nt][3] += (sb + 1 == trow1 + 1) ? 0.f : f1.y;
            pm0 = fmaxf(pm0, fmaxf(pacc[nt][0], pacc[nt][1]));
            pm1 = fmaxf(pm1, fmaxf(pacc[nt][2], pacc[nt][3]));
        }
        pm0 = fmaxf(pm0, __shfl_xor_sync(0xffffffffu, pm0, 1));
        pm0 = fmaxf(pm0, __shfl_xor_sync(0xffffffffu, pm0, 2));
        pm1 = fmaxf(pm1, __shfl_xor_sync(0xffffffffu, pm1, 1));
        pm1 = fmaxf(pm1, __shfl_xor_sync(0xffffffffu, pm1, 2));

        float mn0 = fmaxf(m0r, pm0), mn1 = fmaxf(m1r, pm1);
        float sf0 = ex2f(m0r - mn0), sf1 = ex2f(m1r - mn1);
        m0r = mn0; m1r = mn1;
        #pragma unroll
        for (int nt = 0; nt < 8; nt++) {
            oacc[nt][0] *= sf0; oacc[nt][1] *= sf0;
            oacc[nt][2] *= sf1; oacc[nt][3] *= sf1;
        }
        l0 *= sf0; l1 *= sf1;

        // ---- exp, rowsum, pack P to fp16 IN REGISTERS ----
        unsigned ph[8][2];
        float sum0 = 0.f, sum1 = 0.f;
        #pragma unroll
        for (int nt = 0; nt < 8; nt++) {
            float e0 = ex2f(pacc[nt][0] - mn0);
            float e1 = ex2f(pacc[nt][1] - mn0);
            float e2 = ex2f(pacc[nt][2] - mn1);
            float e3 = ex2f(pacc[nt][3] - mn1);
            sum0 += e0 + e1; sum1 += e2 + e3;
            __half2 p0 = __floats2half2_rn(e0, e1);
            __half2 p1 = __floats2half2_rn(e2, e3);
            ph[nt][0] = *(unsigned*)&p0;
            ph[nt][1] = *(unsigned*)&p1;
        }
        sum0 += __shfl_xor_sync(0xffffffffu, sum0, 1);
        sum0 += __shfl_xor_sync(0xffffffffu, sum0, 2);
        sum1 += __shfl_xor_sync(0xffffffffu, sum1, 1);
        sum1 += __shfl_xor_sync(0xffffffffu, sum1, 2);
        l0 += sum0; l1 += sum1;

        // ---- O += P · V (fp16; A-frag from registers, B-frag half2 LDS) ----
        #pragma unroll
        for (int kc = 0; kc < 4; kc++) {
            unsigned af[4] = { ph[2*kc][0], ph[2*kc][1], ph[2*kc+1][0], ph[2*kc+1][1] };
            #pragma unroll
            for (int nt = 0; nt < 8; nt++) {
                int drow = nt * 8 + r;
                unsigned bf[2];
                bf[0] = Vb[drow * 36 + kc * 8 + cc];       // V[d][kc*16+2cc..+1]
                bf[1] = Vb[drow * 36 + kc * 8 + cc + 4];   // V[d][kc*16+8+2cc..+1]
                MMA16(oacc[nt], af, bf);
            }
        }
        __syncwarp();

        if (it < T_ / 64 - 1)
            PREFETCH_BD(s0 + 64);
    }
    asm volatile("cp.async.wait_group 0;" ::: "memory");

    // ---- epilogue: O /= l -> g_ctx (fp16) ----
    float il0 = 1.f / l0, il1 = 1.f / l1;
    #pragma unroll
    for (int nt = 0; nt < 8; nt++) {
        int d = h * 64 + nt * 8 + 2 * cc;
        __half2 o0 = __floats2half2_rn(oacc[nt][0] * il0, oacc[nt][1] * il0);
        *(__half2*)(g_ctx + ((size_t)trow0 * B_ + b) * E_ + d) = o0;
        __half2 o1 = __floats2half2_rn(oacc[nt][2] * il1, oacc[nt][3] * il1);
        *(__half2*)(g_ctx + ((size_t)trow1 * B_ + b) * E_ + d) = o1;
    }
#undef PREFETCH_KV
#undef PREFETCH_BD
}

// ============================================================
// out projection (fp16 GEMM, fp32 output)
// ============================================================
__global__ __launch_bounds__(256) void k_out(const float* __restrict__ bias,
                                             float* __restrict__ out) {
    extern __shared__ unsigned dsm[];
    float acc[4][4][4] = {};
    const int m0 = blockIdx.y * 128, n0 = blockIdx.x * 128;
    gemm_nt_hp<E_>(g_ctx, E_, g_cwout, E_, m0, n0, acc, dsm);
    const int lane = threadIdx.x & 31, warp = threadIdx.x >> 5;
    const int wm = (warp >> 2) * 64, wn = (warp & 3) * 32;
    #pragma unroll
    for (int mi = 0; mi < 4; mi++)
        #pragma unroll
        for (int ni = 0; ni < 4; ni++)
            #pragma unroll
            for (int rg = 0; rg < 4; rg++) {
                int row = EPI_ROW(m0, wm, mi, rg);
                int col = EPI_COL(n0, wn, ni, rg);
                out[(size_t)row * E_ + col] = acc[mi][ni][rg] + bias[col];
            }
}

// ============================================================
extern "C" void kernel_launch(void* const* d_in, const int* in_sizes, int n_in,
                              void* d_out, int out_size) {
    const float* input = (const float*)d_in[0];
    const float* pos   = (const float*)d_in[1];
    const float* w_in  = (const float*)d_in[2];
    const float* w_out = (const float*)d_in[3];
    const float* w_pos = (const float*)d_in[4];
    const float* b_in  = (const float*)d_in[5];
    const float* b_out = (const float*)d_in[6];
    const float* b_pos = (const float*)d_in[7];
    const float* rwb   = (const float*)d_in[8];
    const float* rrb   = (const float*)d_in[9];
    float* out = (float*)d_out;

    const int gemm_smem  = 2 * 2 * 128 * 20 * 4;                 // 40960
    const int bd_smem    = 128 * 136 * 2;                        // 34816
    const int kbd_smem   = gemm_smem > bd_smem ? gemm_smem : bd_smem;
    const int flash_smem = (2 * (64*40 + 64*36) + 128*36) * 4;   // 57344
    cudaFuncSetAttribute(k_qkv,  cudaFuncAttributeMaxDynamicSharedMemorySize, gemm_smem);
    cudaFuncSetAttribute(k_pos,  cudaFuncAttributeMaxDynamicSharedMemorySize, gemm_smem);
    cudaFuncSetAttribute(k_bd,   cudaFuncAttributeMaxDynamicSharedMemorySize, kbd_smem);
    cudaFuncSetAttribute(k_out,  cudaFuncAttributeMaxDynamicSharedMemorySize, gemm_smem);
    cudaFuncSetAttribute(k_flash, cudaFuncAttributeMaxDynamicSharedMemorySize, flash_smem);

    k_cvt_all<<<(N4_TOT + 255)/256, 256>>>(input, pos, w_in, w_out, w_pos);

    k_qkv  <<<dim3(E3_/128, (T_*B_)/128), 256, gemm_smem>>>(b_in);
    k_pos  <<<dim3(E_/128,  T_/128),      256, gemm_smem>>>(b_pos);
    k_brdot<<<H_*T_/128, 128>>>(rrb);
    k_bd   <<<dim3(T_/128, T_/128, B_*H_), 256, kbd_smem>>>();
    k_flash<<<dim3(T_/128, B_*H_), 256, flash_smem>>>(rwb);
    k_out  <<<dim3(E_/128, (T_*B_)/128), 256, gemm_smem>>>(b_out, out);
}